// round 10
// baseline (speedup 1.0000x reference)
#include <cuda_runtime.h>
#include <cuda_fp16.h>
#include <cstdint>
#include <math.h>

// Problem constants
#define TOKENS 8192        // b*n = 4*2048
#define DIM    512
#define CODES  8192
#define DECAYF 0.8f
#define OMDF   (1.0f - 0.8f)
#define EPSF   1e-5f
#define MARGIN 3e-3f
#define NTILES 128         // 64-col tiles per row

// Output layout (floats), tuple order flattened
#define OFF_Q    ((size_t)0)
#define OFF_IND  ((size_t)4194304)
#define OFF_DIST ((size_t)4202496)
#define OFF_CS   ((size_t)71311360)
#define OFF_EA   ((size_t)71319552)
#define OFF_E    ((size_t)75513856)

// Scratch (device globals; no allocations allowed)
__device__ float g_xn[(size_t)TOKENS * DIM];   // l2-normalized x (fp32)
__device__ int   g_ind[TOKENS];
__device__ float g_denom;
__device__ __half g_A[(size_t)TOKENS * DIM];   // fp16(xn)
__device__ __half g_B[(size_t)CODES  * DIM];   // fp16(embed)
__device__ float g_tilemax[(size_t)TOKENS * NTILES];  // per (row, 64-col tile) max

// ---------------------------------------------------------------------------
// helpers
// ---------------------------------------------------------------------------
__device__ __forceinline__ uint32_t smem_u32(const void* p) {
    uint32_t a;
    asm("{ .reg .u64 t; cvta.to.shared.u64 t, %1; cvt.u32.u64 %0, t; }" : "=r"(a) : "l"(p));
    return a;
}
__device__ __forceinline__ void cp16(uint32_t dst, const void* src) {
    asm volatile("cp.async.cg.shared.global [%0], [%1], 16;" :: "r"(dst), "l"(src));
}
__device__ __forceinline__ void cp_commit() {
    asm volatile("cp.async.commit_group;" ::: "memory");
}
__device__ __forceinline__ void cp_wait1() {
    asm volatile("cp.async.wait_group 1;" ::: "memory");
}
__device__ __forceinline__ void ldsm_x4(uint32_t& r0, uint32_t& r1, uint32_t& r2,
                                        uint32_t& r3, uint32_t addr) {
    asm volatile("ldmatrix.sync.aligned.m8n8.x4.shared.b16 {%0,%1,%2,%3}, [%4];"
                 : "=r"(r0), "=r"(r1), "=r"(r2), "=r"(r3) : "r"(addr));
}
__device__ __forceinline__ void mma_fp16(float& c0, float& c1, float& c2, float& c3,
                                         uint32_t a0, uint32_t a1, uint32_t a2, uint32_t a3,
                                         uint32_t b0, uint32_t b1) {
    asm volatile(
        "mma.sync.aligned.m16n8k16.row.col.f32.f16.f16.f32 "
        "{%0,%1,%2,%3}, {%4,%5,%6,%7}, {%8,%9}, {%0,%1,%2,%3};"
        : "+f"(c0), "+f"(c1), "+f"(c2), "+f"(c3)
        : "r"(a0), "r"(a1), "r"(a2), "r"(a3), "r"(b0), "r"(b1));
}

// ---------------------------------------------------------------------------
// K1: fused prep. Blocks [0, TOKENS): l2-normalize x -> g_xn + g_A(fp16).
//     Blocks [TOKENS, TOKENS+CODES): g_B = fp16(embed).
// ---------------------------------------------------------------------------
__global__ void k_prep(const float* __restrict__ x, const float* __restrict__ embed) {
    int b = blockIdx.x;
    if (b >= TOKENS) {
        int c = b - TOKENS;
        float4 a = ((const float4*)(embed + (size_t)c * DIM))[threadIdx.x];
        __half* rB = g_B + (size_t)c * DIM;
        int d = threadIdx.x * 4;
        *(__half2*)(rB + d)     = __half2(__float2half_rn(a.x), __float2half_rn(a.y));
        *(__half2*)(rB + d + 2) = __half2(__float2half_rn(a.z), __float2half_rn(a.w));
        return;
    }
    int t = b;
    const float4* row = (const float4*)(x + (size_t)t * DIM);
    float4 a = row[threadIdx.x];                 // 128 threads * 4 = 512
    float ss = a.x * a.x + a.y * a.y + a.z * a.z + a.w * a.w;
    #pragma unroll
    for (int o = 16; o > 0; o >>= 1) ss += __shfl_xor_sync(0xffffffffu, ss, o);
    __shared__ float warpsum[4];
    __shared__ float s_inv;
    if ((threadIdx.x & 31) == 0) warpsum[threadIdx.x >> 5] = ss;
    __syncthreads();
    if (threadIdx.x == 0) {
        float tot = warpsum[0] + warpsum[1] + warpsum[2] + warpsum[3];
        s_inv = 1.0f / fmaxf(sqrtf(tot), 1e-6f);
    }
    __syncthreads();
    float inv = s_inv;
    float v[4] = {a.x * inv, a.y * inv, a.z * inv, a.w * inv};
    ((float4*)(g_xn + (size_t)t * DIM))[threadIdx.x] = make_float4(v[0], v[1], v[2], v[3]);
    __half* rA = g_A + (size_t)t * DIM;
    int c = threadIdx.x * 4;
    *(__half2*)(rA + c)     = __half2(__float2half_rn(v[0]), __float2half_rn(v[1]));
    *(__half2*)(rA + c + 2) = __half2(__float2half_rn(v[2]), __float2half_rn(v[3]));
}

// ---------------------------------------------------------------------------
// K2: dist = g_A @ g_B^T via mma.sync fp16, K=512, plus per-tile row max.
// CTA tile 128x64, BK=32, 3-stage cp.async ring, 8 warps (4M x 2N), warp 32x32.
// Low regs (~70) -> 3+ CTAs/SM for latency hiding.
// ---------------------------------------------------------------------------
#define BK       32
#define NITERS   (DIM / BK)            // 16
#define NSTAGES  3
#define ASTRIDE  40                    // fp16 elems per smem row (32 + 8 pad)
#define ATILE_B  (128 * ASTRIDE * 2)   // 10240 bytes
#define BTILE_B  (64 * ASTRIDE * 2)    // 5120 bytes
#define STAGE_B  (ATILE_B + BTILE_B)   // 15360 bytes
#define SMEM_TOT (NSTAGES * STAGE_B)   // 46080 bytes

extern __shared__ char dyn_smem[];

__device__ __forceinline__ void load_tile(uint32_t sbase, int stage, int iter,
                                          int tid, int rowBase, int colBase) {
    int k0 = iter * BK;
    uint32_t st = sbase + stage * STAGE_B;
    #pragma unroll
    for (int i = 0; i < 3; i++) {
        int q = i * 256 + tid;            // 0..767
        int isA = q < 512;
        int qq = isA ? q : q - 512;
        int row = qq >> 2;
        int seg = qq & 3;                 // 8 fp16 (16B) per seg
        const __half* src =
            (isA ? g_A + (size_t)(rowBase + row) * DIM
                 : g_B + (size_t)(colBase + row) * DIM) + k0 + seg * 8;
        uint32_t dst = st + (isA ? 0 : ATILE_B) + (row * ASTRIDE + seg * 8) * 2;
        cp16(dst, src);
    }
}

__global__ void __launch_bounds__(256, 3)
k_gemm_mma(float* __restrict__ dist) {
    __shared__ float s_rm[128][2];
    uint32_t sbase = smem_u32(dyn_smem);
    int tid  = threadIdx.x;
    int wid  = tid >> 5;
    int lane = tid & 31;
    int warpM = wid & 3;       // 0..3  (32 rows each)
    int warpN = wid >> 2;      // 0..1  (32 cols each)
    int rowBase = blockIdx.y * 128;
    int colBase = blockIdx.x * 64;

    float acc[2][4][4];
    #pragma unroll
    for (int mi = 0; mi < 2; mi++)
        #pragma unroll
        for (int ni = 0; ni < 4; ni++)
            #pragma unroll
            for (int r = 0; r < 4; r++) acc[mi][ni][r] = 0.0f;

    // A ldmatrix lane mapping (x4: rows 0-7/8-15 at k0, rows 0-7/8-15 at k8)
    int amat = lane >> 3, ar = lane & 7;
    int arow_in = (amat & 1) * 8 + ar;
    int ak_in   = (amat >> 1) * 8;
    // B merged-x4 lane mapping (m0: r0-7 k0, m1: r0-7 k8, m2: r8-15 k0, m3: r8-15 k8)
    int bm = lane >> 3;
    int brow_in = (lane & 7) + ((bm >> 1) << 3);
    int bk_in   = (bm & 1) * 8;

    load_tile(sbase, 0, 0, tid, rowBase, colBase);
    cp_commit();
    load_tile(sbase, 1, 1, tid, rowBase, colBase);
    cp_commit();

    for (int it = 0; it < NITERS; it++) {
        int stage = it % NSTAGES;
        cp_wait1();
        __syncthreads();
        if (it + 2 < NITERS)
            load_tile(sbase, (it + 2) % NSTAGES, it + 2, tid, rowBase, colBase);
        cp_commit();

        uint32_t sA = sbase + stage * STAGE_B;
        uint32_t sB = sA + ATILE_B;
        #pragma unroll
        for (int ks = 0; ks < 2; ks++) {
            uint32_t aa[2][4];
            #pragma unroll
            for (int mi = 0; mi < 2; mi++) {
                uint32_t addr = sA +
                    ((warpM * 32 + mi * 16 + arow_in) * ASTRIDE + ks * 16 + ak_in) * 2;
                ldsm_x4(aa[mi][0], aa[mi][1], aa[mi][2], aa[mi][3], addr);
            }
            uint32_t bb[2][4];
            #pragma unroll
            for (int np = 0; np < 2; np++) {
                uint32_t addr = sB +
                    ((warpN * 32 + np * 16 + brow_in) * ASTRIDE + ks * 16 + bk_in) * 2;
                ldsm_x4(bb[np][0], bb[np][1], bb[np][2], bb[np][3], addr);
            }
            #pragma unroll
            for (int mi = 0; mi < 2; mi++)
                #pragma unroll
                for (int ni = 0; ni < 4; ni++)
                    mma_fp16(acc[mi][ni][0], acc[mi][ni][1], acc[mi][ni][2], acc[mi][ni][3],
                             aa[mi][0], aa[mi][1], aa[mi][2], aa[mi][3],
                             bb[ni >> 1][(ni & 1) * 2], bb[ni >> 1][(ni & 1) * 2 + 1]);
        }
    }

    // Epilogue: write dist + per-warp row maxes
    int g = lane >> 2;
    int cq = (lane & 3) * 2;
    #pragma unroll
    for (int mi = 0; mi < 2; mi++) {
        int r0 = rowBase + warpM * 32 + mi * 16 + g;
        float mlo = -INFINITY, mhi = -INFINITY;
        #pragma unroll
        for (int ni = 0; ni < 4; ni++) {
            int cc = colBase + warpN * 32 + ni * 8 + cq;
            *(float2*)(dist + (size_t)r0 * CODES + cc) =
                make_float2(acc[mi][ni][0], acc[mi][ni][1]);
            *(float2*)(dist + (size_t)(r0 + 8) * CODES + cc) =
                make_float2(acc[mi][ni][2], acc[mi][ni][3]);
            mlo = fmaxf(mlo, fmaxf(acc[mi][ni][0], acc[mi][ni][1]));
            mhi = fmaxf(mhi, fmaxf(acc[mi][ni][2], acc[mi][ni][3]));
        }
        #pragma unroll
        for (int o = 1; o < 4; o <<= 1) {
            mlo = fmaxf(mlo, __shfl_xor_sync(0xffffffffu, mlo, o));
            mhi = fmaxf(mhi, __shfl_xor_sync(0xffffffffu, mhi, o));
        }
        if ((lane & 3) == 0) {
            s_rm[warpM * 32 + mi * 16 + g][warpN]     = mlo;
            s_rm[warpM * 32 + mi * 16 + g + 8][warpN] = mhi;
        }
    }
    __syncthreads();
    if (tid < 128) {
        float m = fmaxf(s_rm[tid][0], s_rm[tid][1]);
        g_tilemax[(size_t)(rowBase + tid) * NTILES + blockIdx.x] = m;
    }
}

// ---------------------------------------------------------------------------
// K3: per-row candidate refinement + exact fp32 argmax + quantize gather
//     + fused EMA scatter (out_ea/out_cs pre-initialized to DECAY*old).
// One block (128 threads) per token row. Tiles are 64 cols wide (128 of them).
// ---------------------------------------------------------------------------
__global__ void __launch_bounds__(128)
k_select(const float* __restrict__ dist, const float* __restrict__ embed,
         float* __restrict__ out_ind, float* __restrict__ out_q,
         float* __restrict__ out_cs, float* __restrict__ out_ea) {
    int t = blockIdx.x;
    int tid = threadIdx.x;
    int wid = tid >> 5, lane = tid & 31;

    __shared__ float s_tm[NTILES];
    __shared__ float s_M;
    __shared__ int   s_cand[64];
    __shared__ int   s_ncand;
    __shared__ float s_red[4];
    __shared__ int   s_best;

    s_tm[tid] = g_tilemax[(size_t)t * NTILES + tid];
    if (tid == 0) s_ncand = 0;
    __syncthreads();
    if (tid < 32) {
        float m = fmaxf(fmaxf(s_tm[tid], s_tm[tid + 32]),
                        fmaxf(s_tm[tid + 64], s_tm[tid + 96]));
        #pragma unroll
        for (int o = 16; o > 0; o >>= 1) m = fmaxf(m, __shfl_xor_sync(0xffffffffu, m, o));
        if (tid == 0) s_M = m;
    }
    __syncthreads();
    float thr = s_M - MARGIN;
    const float* drow = dist + (size_t)t * CODES;
    for (int tile = 0; tile < NTILES; tile++) {
        if (s_tm[tile] > thr && tid < 64) {
            float v = drow[tile * 64 + tid];
            if (v > thr) {
                int p = atomicAdd(&s_ncand, 1);
                if (p < 64) s_cand[p] = tile * 64 + tid;
            }
        }
    }
    __syncthreads();
    int nc = min(s_ncand, 64);

    float4 xv = ((const float4*)(g_xn + (size_t)t * DIM))[tid];
    float bestv = -INFINITY;
    int   besti = CODES;
    for (int ci = 0; ci < nc; ci++) {
        int c = s_cand[ci];
        float4 ev = ((const float4*)(embed + (size_t)c * DIM))[tid];
        float p = xv.x * ev.x + xv.y * ev.y + xv.z * ev.z + xv.w * ev.w;
        #pragma unroll
        for (int o = 16; o > 0; o >>= 1) p += __shfl_xor_sync(0xffffffffu, p, o);
        if (lane == 0) s_red[wid] = p;
        __syncthreads();
        if (tid == 0) {
            float d = (s_red[0] + s_red[1]) + (s_red[2] + s_red[3]);
            if (d > bestv || (d == bestv && c < besti)) { bestv = d; besti = c; }
        }
        __syncthreads();
    }
    if (tid == 0) {
        g_ind[t] = besti;
        out_ind[t] = (float)besti;
        s_best = besti;
        atomicAdd(out_cs + besti, OMDF);
    }
    __syncthreads();
    int best = s_best;
    // quantize gather
    float4 ev = ((const float4*)(embed + (size_t)best * DIM))[tid];
    ((float4*)(out_q + (size_t)t * DIM))[tid] = ev;
    // fused EMA scatter: out_ea[best] += (1-decay) * xn
    float* er = out_ea + (size_t)best * DIM + tid * 4;
    atomicAdd(er + 0, OMDF * xv.x);
    atomicAdd(er + 1, OMDF * xv.y);
    atomicAdd(er + 2, OMDF * xv.z);
    atomicAdd(er + 3, OMDF * xv.w);
}

// ---------------------------------------------------------------------------
// K5a: init EMA outputs with DECAY * old (runs BEFORE k_select)
// ---------------------------------------------------------------------------
__global__ void k_init_ema(const float* __restrict__ cs, const float* __restrict__ ea,
                           float* __restrict__ out_cs, float* __restrict__ out_ea) {
    size_t total = (size_t)CODES * DIM;
    for (size_t i = blockIdx.x * (size_t)blockDim.x + threadIdx.x; i < total;
         i += (size_t)gridDim.x * blockDim.x) {
        out_ea[i] = DECAYF * ea[i];
        if (i < CODES) out_cs[i] = DECAYF * cs[i];
    }
}

// ---------------------------------------------------------------------------
// K6: denom = sum(new_cluster_size)
// ---------------------------------------------------------------------------
__global__ void k_denom(const float* __restrict__ out_cs) {
    float s = 0.0f;
    for (int i = threadIdx.x; i < CODES; i += 1024) s += out_cs[i];
    #pragma unroll
    for (int o = 16; o > 0; o >>= 1) s += __shfl_xor_sync(0xffffffffu, s, o);
    __shared__ float ws[32];
    if ((threadIdx.x & 31) == 0) ws[threadIdx.x >> 5] = s;
    __syncthreads();
    if (threadIdx.x == 0) {
        float tot = 0.0f;
        for (int i = 0; i < 32; i++) tot += ws[i];
        g_denom = tot;
    }
}

// ---------------------------------------------------------------------------
// K7: new_embed = l2norm(new_embed_avg / smoothed)
// ---------------------------------------------------------------------------
__global__ void k_newembed(const float* __restrict__ out_cs,
                           const float* __restrict__ out_ea,
                           float* __restrict__ out_e) {
    int c = blockIdx.x;
    float denom = g_denom;
    float smoothed = (out_cs[c] + EPSF) / (denom + (float)CODES * EPSF) * denom;
    float invs = 1.0f / smoothed;
    float4 v = ((const float4*)(out_ea + (size_t)c * DIM))[threadIdx.x];
    float4 w = make_float4(v.x * invs, v.y * invs, v.z * invs, v.w * invs);
    float ss = w.x * w.x + w.y * w.y + w.z * w.z + w.w * w.w;
    #pragma unroll
    for (int o = 16; o > 0; o >>= 1) ss += __shfl_xor_sync(0xffffffffu, ss, o);
    __shared__ float warpsum[4];
    __shared__ float s_inv;
    if ((threadIdx.x & 31) == 0) warpsum[threadIdx.x >> 5] = ss;
    __syncthreads();
    if (threadIdx.x == 0) {
        float tot = warpsum[0] + warpsum[1] + warpsum[2] + warpsum[3];
        s_inv = 1.0f / fmaxf(sqrtf(tot), 1e-6f);
    }
    __syncthreads();
    float inv = s_inv;
    float4 o4 = make_float4(w.x * inv, w.y * inv, w.z * inv, w.w * inv);
    ((float4*)(out_e + (size_t)c * DIM))[threadIdx.x] = o4;
}

// ---------------------------------------------------------------------------
extern "C" void kernel_launch(void* const* d_in, const int* in_sizes, int n_in,
                              void* d_out, int out_size) {
    const float* x     = (const float*)d_in[0];
    const float* embed = (const float*)d_in[1];
    const float* cs    = (const float*)d_in[2];
    const float* ea    = (const float*)d_in[3];
    float* out = (float*)d_out;

    cudaFuncSetAttribute(k_gemm_mma, cudaFuncAttributeMaxDynamicSharedMemorySize,
                         SMEM_TOT);

    k_prep<<<TOKENS + CODES, 128>>>(x, embed);
    k_init_ema<<<2048, 256>>>(cs, ea, out + OFF_CS, out + OFF_EA);
    k_gemm_mma<<<dim3(CODES / 64, TOKENS / 128), 256, SMEM_TOT>>>(out + OFF_DIST);
    k_select<<<TOKENS, 128>>>(out + OFF_DIST, embed, out + OFF_IND, out + OFF_Q,
                              out + OFF_CS, out + OFF_EA);
    k_denom<<<1, 1024>>>(out + OFF_CS);
    k_newembed<<<CODES, 128>>>(out + OFF_CS, out + OFF_EA, out + OFF_E);
}

// round 11
// speedup vs baseline: 1.0310x; 1.0310x over previous
#include <cuda_runtime.h>
#include <cuda_fp16.h>
#include <cstdint>
#include <math.h>

// Problem constants
#define TOKENS 8192        // b*n = 4*2048
#define DIM    512
#define CODES  8192
#define DECAYF 0.8f
#define OMDF   (1.0f - 0.8f)
#define EPSF   1e-5f
#define MARGIN 3e-3f

// Output layout (floats), tuple order flattened
#define OFF_Q    ((size_t)0)
#define OFF_IND  ((size_t)4194304)
#define OFF_DIST ((size_t)4202496)
#define OFF_CS   ((size_t)71311360)
#define OFF_EA   ((size_t)71319552)
#define OFF_E    ((size_t)75513856)

// Scratch (device globals; no allocations allowed)
__device__ float g_xn[(size_t)TOKENS * DIM];   // l2-normalized x (fp32)
__device__ int   g_ind[TOKENS];
__device__ float g_denom;
__device__ __half g_A[(size_t)TOKENS * DIM];   // fp16(xn)
__device__ __half g_B[(size_t)CODES  * DIM];   // fp16(embed)
__device__ float g_tilemax[(size_t)TOKENS * 64];  // per (row, 128-col tile) max

// ---------------------------------------------------------------------------
// helpers
// ---------------------------------------------------------------------------
__device__ __forceinline__ uint32_t smem_u32(const void* p) {
    uint32_t a;
    asm("{ .reg .u64 t; cvta.to.shared.u64 t, %1; cvt.u32.u64 %0, t; }" : "=r"(a) : "l"(p));
    return a;
}
__device__ __forceinline__ void cp16(uint32_t dst, const void* src) {
    asm volatile("cp.async.cg.shared.global [%0], [%1], 16;" :: "r"(dst), "l"(src));
}
__device__ __forceinline__ void cp_commit() {
    asm volatile("cp.async.commit_group;" ::: "memory");
}
__device__ __forceinline__ void cp_wait2() {
    asm volatile("cp.async.wait_group 2;" ::: "memory");
}
__device__ __forceinline__ void ldsm_x4(uint32_t& r0, uint32_t& r1, uint32_t& r2,
                                        uint32_t& r3, uint32_t addr) {
    asm volatile("ldmatrix.sync.aligned.m8n8.x4.shared.b16 {%0,%1,%2,%3}, [%4];"
                 : "=r"(r0), "=r"(r1), "=r"(r2), "=r"(r3) : "r"(addr));
}
__device__ __forceinline__ void ldsm_x2(uint32_t& r0, uint32_t& r1, uint32_t addr) {
    asm volatile("ldmatrix.sync.aligned.m8n8.x2.shared.b16 {%0,%1}, [%2];"
                 : "=r"(r0), "=r"(r1) : "r"(addr));
}
__device__ __forceinline__ void mma_fp16(float& c0, float& c1, float& c2, float& c3,
                                         uint32_t a0, uint32_t a1, uint32_t a2, uint32_t a3,
                                         uint32_t b0, uint32_t b1) {
    asm volatile(
        "mma.sync.aligned.m16n8k16.row.col.f32.f16.f16.f32 "
        "{%0,%1,%2,%3}, {%4,%5,%6,%7}, {%8,%9}, {%0,%1,%2,%3};"
        : "+f"(c0), "+f"(c1), "+f"(c2), "+f"(c3)
        : "r"(a0), "r"(a1), "r"(a2), "r"(a3), "r"(b0), "r"(b1));
}

// ---------------------------------------------------------------------------
// K1: fused prep. Blocks [0, TOKENS): l2-normalize x -> g_xn + g_A(fp16).
//     Blocks [TOKENS, TOKENS+CODES): g_B = fp16(embed).
// ---------------------------------------------------------------------------
__global__ void k_prep(const float* __restrict__ x, const float* __restrict__ embed) {
    int b = blockIdx.x;
    if (b >= TOKENS) {
        int c = b - TOKENS;
        float4 a = ((const float4*)(embed + (size_t)c * DIM))[threadIdx.x];
        __half* rB = g_B + (size_t)c * DIM;
        int d = threadIdx.x * 4;
        *(__half2*)(rB + d)     = __half2(__float2half_rn(a.x), __float2half_rn(a.y));
        *(__half2*)(rB + d + 2) = __half2(__float2half_rn(a.z), __float2half_rn(a.w));
        return;
    }
    int t = b;
    const float4* row = (const float4*)(x + (size_t)t * DIM);
    float4 a = row[threadIdx.x];                 // 128 threads * 4 = 512
    float ss = a.x * a.x + a.y * a.y + a.z * a.z + a.w * a.w;
    #pragma unroll
    for (int o = 16; o > 0; o >>= 1) ss += __shfl_xor_sync(0xffffffffu, ss, o);
    __shared__ float warpsum[4];
    __shared__ float s_inv;
    if ((threadIdx.x & 31) == 0) warpsum[threadIdx.x >> 5] = ss;
    __syncthreads();
    if (threadIdx.x == 0) {
        float tot = warpsum[0] + warpsum[1] + warpsum[2] + warpsum[3];
        s_inv = 1.0f / fmaxf(sqrtf(tot), 1e-6f);
    }
    __syncthreads();
    float inv = s_inv;
    float v[4] = {a.x * inv, a.y * inv, a.z * inv, a.w * inv};
    ((float4*)(g_xn + (size_t)t * DIM))[threadIdx.x] = make_float4(v[0], v[1], v[2], v[3]);
    __half* rA = g_A + (size_t)t * DIM;
    int c = threadIdx.x * 4;
    *(__half2*)(rA + c)     = __half2(__float2half_rn(v[0]), __float2half_rn(v[1]));
    *(__half2*)(rA + c + 2) = __half2(__float2half_rn(v[2]), __float2half_rn(v[3]));
}

// ---------------------------------------------------------------------------
// K2: dist = g_A @ g_B^T via mma.sync fp16 (HMMA), K=512, plus per-tile row max.
// 128x128 tile, BK=32, 4-stage cp.async ring (prefetch distance 3, wait_group 2),
// 8 warps (2 M x 4 N), warp 64x32; 2 CTAs/SM. Streaming (__stcs) dist stores.
// ---------------------------------------------------------------------------
#define BK       32
#define NITERS   (DIM / BK)            // 16
#define NSTAGES  4
#define ASTRIDE  40                    // fp16 elems per smem row (32 + 8 pad)
#define ATILE_B  (128 * ASTRIDE * 2)   // 10240 bytes
#define STAGE_B  (2 * ATILE_B)         // 20480 bytes (A + B)
#define SMEM_TOT (NSTAGES * STAGE_B)   // 81920 bytes

extern __shared__ char dyn_smem[];

__device__ __forceinline__ void load_tile(uint32_t sbase, int stage, int iter,
                                          int tid, int rowBase, int colBase) {
    int k0 = iter * BK;
    uint32_t st = sbase + stage * STAGE_B;
    #pragma unroll
    for (int i = 0; i < 4; i++) {
        int q = i * 256 + tid;            // 0..1023
        int isA = q < 512;
        int qq = isA ? q : q - 512;
        int row = qq >> 2;
        int seg = qq & 3;                 // 8 fp16 (16B) per seg
        const __half* src =
            (isA ? g_A + (size_t)(rowBase + row) * DIM
                 : g_B + (size_t)(colBase + row) * DIM) + k0 + seg * 8;
        uint32_t dst = st + (isA ? 0 : ATILE_B) + (row * ASTRIDE + seg * 8) * 2;
        cp16(dst, src);
    }
}

__global__ void __launch_bounds__(256, 2)
k_gemm_mma(float* __restrict__ dist) {
    __shared__ float s_rm[128][4];
    uint32_t sbase = smem_u32(dyn_smem);
    int tid  = threadIdx.x;
    int wid  = tid >> 5;
    int lane = tid & 31;
    int warpM = wid >> 2;      // 0..1  (64 rows each)
    int warpN = wid & 3;       // 0..3  (32 cols each)
    int rowBase = blockIdx.y * 128;
    int colBase = blockIdx.x * 128;

    float acc[4][4][4];
    #pragma unroll
    for (int mi = 0; mi < 4; mi++)
        #pragma unroll
        for (int ni = 0; ni < 4; ni++)
            #pragma unroll
            for (int r = 0; r < 4; r++) acc[mi][ni][r] = 0.0f;

    int amat = lane >> 3, ar = lane & 7;
    int arow_in = (amat & 1) * 8 + ar;
    int ak_in   = (amat >> 1) * 8;
    int ml = lane & 15;
    int brow_in = ml & 7;
    int bk_in   = (ml >> 3) * 8;

    // Prologue: fill 3 stages
    load_tile(sbase, 0, 0, tid, rowBase, colBase);
    cp_commit();
    load_tile(sbase, 1, 1, tid, rowBase, colBase);
    cp_commit();
    load_tile(sbase, 2, 2, tid, rowBase, colBase);
    cp_commit();

    for (int it = 0; it < NITERS; it++) {
        int stage = it % NSTAGES;
        cp_wait2();            // stage `it` complete (<=2 younger groups pending)
        __syncthreads();
        if (it + 3 < NITERS)
            load_tile(sbase, (it + 3) % NSTAGES, it + 3, tid, rowBase, colBase);
        cp_commit();

        uint32_t sA = sbase + stage * STAGE_B;
        uint32_t sB = sA + ATILE_B;
        #pragma unroll
        for (int ks = 0; ks < 2; ks++) {
            uint32_t a0[4], a1[4], a2[4], a3[4];
            #pragma unroll
            for (int mi = 0; mi < 4; mi++) {
                uint32_t addr = sA +
                    ((warpM * 64 + mi * 16 + arow_in) * ASTRIDE + ks * 16 + ak_in) * 2;
                ldsm_x4(a0[mi], a1[mi], a2[mi], a3[mi], addr);
            }
            uint32_t b0[4], b1[4];
            #pragma unroll
            for (int ni = 0; ni < 4; ni++) {
                uint32_t addr = sB +
                    ((warpN * 32 + ni * 8 + brow_in) * ASTRIDE + ks * 16 + bk_in) * 2;
                ldsm_x2(b0[ni], b1[ni], addr);
            }
            #pragma unroll
            for (int mi = 0; mi < 4; mi++)
                #pragma unroll
                for (int ni = 0; ni < 4; ni++)
                    mma_fp16(acc[mi][ni][0], acc[mi][ni][1], acc[mi][ni][2], acc[mi][ni][3],
                             a0[mi], a1[mi], a2[mi], a3[mi], b0[ni], b1[ni]);
        }
    }

    // Epilogue: streaming dist stores + per-warp row maxes
    int g = lane >> 2;
    int cq = (lane & 3) * 2;
    #pragma unroll
    for (int mi = 0; mi < 4; mi++) {
        int r0 = rowBase + warpM * 64 + mi * 16 + g;
        float mlo = -INFINITY, mhi = -INFINITY;
        #pragma unroll
        for (int ni = 0; ni < 4; ni++) {
            int cc = colBase + warpN * 32 + ni * 8 + cq;
            __stcs((float2*)(dist + (size_t)r0 * CODES + cc),
                   make_float2(acc[mi][ni][0], acc[mi][ni][1]));
            __stcs((float2*)(dist + (size_t)(r0 + 8) * CODES + cc),
                   make_float2(acc[mi][ni][2], acc[mi][ni][3]));
            mlo = fmaxf(mlo, fmaxf(acc[mi][ni][0], acc[mi][ni][1]));
            mhi = fmaxf(mhi, fmaxf(acc[mi][ni][2], acc[mi][ni][3]));
        }
        #pragma unroll
        for (int o = 1; o < 4; o <<= 1) {
            mlo = fmaxf(mlo, __shfl_xor_sync(0xffffffffu, mlo, o));
            mhi = fmaxf(mhi, __shfl_xor_sync(0xffffffffu, mhi, o));
        }
        if ((lane & 3) == 0) {
            s_rm[warpM * 64 + mi * 16 + g][warpN]     = mlo;
            s_rm[warpM * 64 + mi * 16 + g + 8][warpN] = mhi;
        }
    }
    __syncthreads();
    if (tid < 128) {
        float m = fmaxf(fmaxf(s_rm[tid][0], s_rm[tid][1]),
                        fmaxf(s_rm[tid][2], s_rm[tid][3]));
        g_tilemax[(size_t)(rowBase + tid) * 64 + blockIdx.x] = m;
    }
}

// ---------------------------------------------------------------------------
// K3: per-row candidate refinement + exact fp32 argmax + quantize gather
//     + fused EMA scatter (out_ea/out_cs pre-initialized to DECAY*old).
// One block (128 threads) per token row. 64 tiles of 128 cols.
// ---------------------------------------------------------------------------
__global__ void __launch_bounds__(128)
k_select(const float* __restrict__ dist, const float* __restrict__ embed,
         float* __restrict__ out_ind, float* __restrict__ out_q,
         float* __restrict__ out_cs, float* __restrict__ out_ea) {
    int t = blockIdx.x;
    int tid = threadIdx.x;
    int wid = tid >> 5, lane = tid & 31;

    __shared__ float s_tm[64];
    __shared__ float s_M;
    __shared__ int   s_cand[64];
    __shared__ int   s_ncand;
    __shared__ float s_red[4];
    __shared__ int   s_best;

    if (tid < 64) s_tm[tid] = g_tilemax[(size_t)t * 64 + tid];
    if (tid == 0) s_ncand = 0;
    __syncthreads();
    if (tid < 32) {
        float m = fmaxf(s_tm[tid], s_tm[tid + 32]);
        #pragma unroll
        for (int o = 16; o > 0; o >>= 1) m = fmaxf(m, __shfl_xor_sync(0xffffffffu, m, o));
        if (tid == 0) s_M = m;
    }
    __syncthreads();
    float thr = s_M - MARGIN;
    const float* drow = dist + (size_t)t * CODES;
    for (int tile = 0; tile < 64; tile++) {
        if (s_tm[tile] > thr) {
            float v = drow[tile * 128 + tid];
            if (v > thr) {
                int p = atomicAdd(&s_ncand, 1);
                if (p < 64) s_cand[p] = tile * 128 + tid;
            }
        }
    }
    __syncthreads();
    int nc = min(s_ncand, 64);

    float4 xv = ((const float4*)(g_xn + (size_t)t * DIM))[tid];
    float bestv = -INFINITY;
    int   besti = CODES;
    for (int ci = 0; ci < nc; ci++) {
        int c = s_cand[ci];
        float4 ev = ((const float4*)(embed + (size_t)c * DIM))[tid];
        float p = xv.x * ev.x + xv.y * ev.y + xv.z * ev.z + xv.w * ev.w;
        #pragma unroll
        for (int o = 16; o > 0; o >>= 1) p += __shfl_xor_sync(0xffffffffu, p, o);
        if (lane == 0) s_red[wid] = p;
        __syncthreads();
        if (tid == 0) {
            float d = (s_red[0] + s_red[1]) + (s_red[2] + s_red[3]);
            if (d > bestv || (d == bestv && c < besti)) { bestv = d; besti = c; }
        }
        __syncthreads();
    }
    if (tid == 0) {
        g_ind[t] = besti;
        out_ind[t] = (float)besti;
        s_best = besti;
        atomicAdd(out_cs + besti, OMDF);
    }
    __syncthreads();
    int best = s_best;
    // quantize gather
    float4 ev = ((const float4*)(embed + (size_t)best * DIM))[tid];
    ((float4*)(out_q + (size_t)t * DIM))[tid] = ev;
    // fused EMA scatter: out_ea[best] += (1-decay) * xn
    float* er = out_ea + (size_t)best * DIM + tid * 4;
    atomicAdd(er + 0, OMDF * xv.x);
    atomicAdd(er + 1, OMDF * xv.y);
    atomicAdd(er + 2, OMDF * xv.z);
    atomicAdd(er + 3, OMDF * xv.w);
}

// ---------------------------------------------------------------------------
// K5a: init EMA outputs with DECAY * old (runs BEFORE k_select)
// ---------------------------------------------------------------------------
__global__ void k_init_ema(const float* __restrict__ cs, const float* __restrict__ ea,
                           float* __restrict__ out_cs, float* __restrict__ out_ea) {
    size_t total = (size_t)CODES * DIM;
    for (size_t i = blockIdx.x * (size_t)blockDim.x + threadIdx.x; i < total;
         i += (size_t)gridDim.x * blockDim.x) {
        out_ea[i] = DECAYF * ea[i];
        if (i < CODES) out_cs[i] = DECAYF * cs[i];
    }
}

// ---------------------------------------------------------------------------
// K6: denom = sum(new_cluster_size)
// ---------------------------------------------------------------------------
__global__ void k_denom(const float* __restrict__ out_cs) {
    float s = 0.0f;
    for (int i = threadIdx.x; i < CODES; i += 1024) s += out_cs[i];
    #pragma unroll
    for (int o = 16; o > 0; o >>= 1) s += __shfl_xor_sync(0xffffffffu, s, o);
    __shared__ float ws[32];
    if ((threadIdx.x & 31) == 0) ws[threadIdx.x >> 5] = s;
    __syncthreads();
    if (threadIdx.x == 0) {
        float tot = 0.0f;
        for (int i = 0; i < 32; i++) tot += ws[i];
        g_denom = tot;
    }
}

// ---------------------------------------------------------------------------
// K7: new_embed = l2norm(new_embed_avg / smoothed)
// ---------------------------------------------------------------------------
__global__ void k_newembed(const float* __restrict__ out_cs,
                           const float* __restrict__ out_ea,
                           float* __restrict__ out_e) {
    int c = blockIdx.x;
    float denom = g_denom;
    float smoothed = (out_cs[c] + EPSF) / (denom + (float)CODES * EPSF) * denom;
    float invs = 1.0f / smoothed;
    float4 v = ((const float4*)(out_ea + (size_t)c * DIM))[threadIdx.x];
    float4 w = make_float4(v.x * invs, v.y * invs, v.z * invs, v.w * invs);
    float ss = w.x * w.x + w.y * w.y + w.z * w.z + w.w * w.w;
    #pragma unroll
    for (int o = 16; o > 0; o >>= 1) ss += __shfl_xor_sync(0xffffffffu, ss, o);
    __shared__ float warpsum[4];
    __shared__ float s_inv;
    if ((threadIdx.x & 31) == 0) warpsum[threadIdx.x >> 5] = ss;
    __syncthreads();
    if (threadIdx.x == 0) {
        float tot = warpsum[0] + warpsum[1] + warpsum[2] + warpsum[3];
        s_inv = 1.0f / fmaxf(sqrtf(tot), 1e-6f);
    }
    __syncthreads();
    float inv = s_inv;
    float4 o4 = make_float4(w.x * inv, w.y * inv, w.z * inv, w.w * inv);
    ((float4*)(out_e + (size_t)c * DIM))[threadIdx.x] = o4;
}

// ---------------------------------------------------------------------------
extern "C" void kernel_launch(void* const* d_in, const int* in_sizes, int n_in,
                              void* d_out, int out_size) {
    const float* x     = (const float*)d_in[0];
    const float* embed = (const float*)d_in[1];
    const float* cs    = (const float*)d_in[2];
    const float* ea    = (const float*)d_in[3];
    float* out = (float*)d_out;

    cudaFuncSetAttribute(k_gemm_mma, cudaFuncAttributeMaxDynamicSharedMemorySize,
                         SMEM_TOT);

    k_prep<<<TOKENS + CODES, 128>>>(x, embed);
    k_init_ema<<<2048, 256>>>(cs, ea, out + OFF_CS, out + OFF_EA);
    k_gemm_mma<<<dim3(CODES / 128, TOKENS / 128), 256, SMEM_TOT>>>(out + OFF_DIST);
    k_select<<<TOKENS, 128>>>(out + OFF_DIST, embed, out + OFF_IND, out + OFF_Q,
                              out + OFF_CS, out + OFF_EA);
    k_denom<<<1, 1024>>>(out + OFF_CS);
    k_newembed<<<CODES, 128>>>(out + OFF_CS, out + OFF_EA, out + OFF_E);
}

// round 12
// speedup vs baseline: 1.1248x; 1.0910x over previous
#include <cuda_runtime.h>
#include <cuda_fp16.h>
#include <cstdint>
#include <math.h>

// Problem constants
#define TOKENS 8192        // b*n = 4*2048
#define DIM    512
#define CODES  8192
#define DECAYF 0.8f
#define OMDF   (1.0f - 0.8f)
#define EPSF   1e-5f
#define MARGIN 3e-3f

// Output layout (floats), tuple order flattened
#define OFF_Q    ((size_t)0)
#define OFF_IND  ((size_t)4194304)
#define OFF_DIST ((size_t)4202496)
#define OFF_CS   ((size_t)71311360)
#define OFF_EA   ((size_t)71319552)
#define OFF_E    ((size_t)75513856)

// Scratch (device globals; no allocations allowed)
__device__ float g_xn[(size_t)TOKENS * DIM];   // l2-normalized x (fp32)
__device__ int   g_ind[TOKENS];
__device__ float g_denom;
__device__ __half g_A[(size_t)TOKENS * DIM];   // fp16(xn)
__device__ __half g_B[(size_t)CODES  * DIM];   // fp16(embed)
__device__ float g_tilemax[(size_t)TOKENS * 64];  // per (row, 128-col tile) max

#define EMA_BLOCKS 2048

// ---------------------------------------------------------------------------
// helpers
// ---------------------------------------------------------------------------
__device__ __forceinline__ uint32_t smem_u32(const void* p) {
    uint32_t a;
    asm("{ .reg .u64 t; cvta.to.shared.u64 t, %1; cvt.u32.u64 %0, t; }" : "=r"(a) : "l"(p));
    return a;
}
__device__ __forceinline__ void cp16(uint32_t dst, const void* src) {
    asm volatile("cp.async.cg.shared.global [%0], [%1], 16;" :: "r"(dst), "l"(src));
}
__device__ __forceinline__ void cp_commit() {
    asm volatile("cp.async.commit_group;" ::: "memory");
}
__device__ __forceinline__ void cp_wait1() {
    asm volatile("cp.async.wait_group 1;" ::: "memory");
}
__device__ __forceinline__ void ldsm_x4(uint32_t& r0, uint32_t& r1, uint32_t& r2,
                                        uint32_t& r3, uint32_t addr) {
    asm volatile("ldmatrix.sync.aligned.m8n8.x4.shared.b16 {%0,%1,%2,%3}, [%4];"
                 : "=r"(r0), "=r"(r1), "=r"(r2), "=r"(r3) : "r"(addr));
}
__device__ __forceinline__ void ldsm_x2(uint32_t& r0, uint32_t& r1, uint32_t addr) {
    asm volatile("ldmatrix.sync.aligned.m8n8.x2.shared.b16 {%0,%1}, [%2];"
                 : "=r"(r0), "=r"(r1) : "r"(addr));
}
__device__ __forceinline__ void mma_fp16(float& c0, float& c1, float& c2, float& c3,
                                         uint32_t a0, uint32_t a1, uint32_t a2, uint32_t a3,
                                         uint32_t b0, uint32_t b1) {
    asm volatile(
        "mma.sync.aligned.m16n8k16.row.col.f32.f16.f16.f32 "
        "{%0,%1,%2,%3}, {%4,%5,%6,%7}, {%8,%9}, {%0,%1,%2,%3};"
        : "+f"(c0), "+f"(c1), "+f"(c2), "+f"(c3)
        : "r"(a0), "r"(a1), "r"(a2), "r"(a3), "r"(b0), "r"(b1));
}

// ---------------------------------------------------------------------------
// K1: fused prep.
//   b in [0, TOKENS):                 l2-normalize x -> g_xn + g_A(fp16)
//   b in [TOKENS, TOKENS+CODES):      g_B = fp16(embed)
//   b in [.., .. + EMA_BLOCKS):       out_ea = decay*ea; out_cs = decay*cs
// ---------------------------------------------------------------------------
__global__ void k_prep(const float* __restrict__ x, const float* __restrict__ embed,
                       const float* __restrict__ cs, const float* __restrict__ ea,
                       float* __restrict__ out_cs, float* __restrict__ out_ea) {
    int b = blockIdx.x;
    if (b >= TOKENS + CODES) {
        int e = b - TOKENS - CODES;                    // 0..EMA_BLOCKS-1
        int gid = e * 128 + threadIdx.x;               // 0..262143
        const float4* ea4 = (const float4*)ea;
        float4* oea4 = (float4*)out_ea;
        for (int i = gid; i < CODES * DIM / 4; i += EMA_BLOCKS * 128) {
            float4 v = ea4[i];
            oea4[i] = make_float4(DECAYF * v.x, DECAYF * v.y, DECAYF * v.z, DECAYF * v.w);
        }
        if (gid < CODES / 4) {
            float4 v = ((const float4*)cs)[gid];
            ((float4*)out_cs)[gid] =
                make_float4(DECAYF * v.x, DECAYF * v.y, DECAYF * v.z, DECAYF * v.w);
        }
        return;
    }
    if (b >= TOKENS) {
        int c = b - TOKENS;
        float4 a = ((const float4*)(embed + (size_t)c * DIM))[threadIdx.x];
        __half* rB = g_B + (size_t)c * DIM;
        int d = threadIdx.x * 4;
        *(__half2*)(rB + d)     = __half2(__float2half_rn(a.x), __float2half_rn(a.y));
        *(__half2*)(rB + d + 2) = __half2(__float2half_rn(a.z), __float2half_rn(a.w));
        return;
    }
    int t = b;
    const float4* row = (const float4*)(x + (size_t)t * DIM);
    float4 a = row[threadIdx.x];                 // 128 threads * 4 = 512
    float ss = a.x * a.x + a.y * a.y + a.z * a.z + a.w * a.w;
    #pragma unroll
    for (int o = 16; o > 0; o >>= 1) ss += __shfl_xor_sync(0xffffffffu, ss, o);
    __shared__ float warpsum[4];
    __shared__ float s_inv;
    if ((threadIdx.x & 31) == 0) warpsum[threadIdx.x >> 5] = ss;
    __syncthreads();
    if (threadIdx.x == 0) {
        float tot = warpsum[0] + warpsum[1] + warpsum[2] + warpsum[3];
        s_inv = 1.0f / fmaxf(sqrtf(tot), 1e-6f);
    }
    __syncthreads();
    float inv = s_inv;
    float v[4] = {a.x * inv, a.y * inv, a.z * inv, a.w * inv};
    ((float4*)(g_xn + (size_t)t * DIM))[threadIdx.x] = make_float4(v[0], v[1], v[2], v[3]);
    __half* rA = g_A + (size_t)t * DIM;
    int c = threadIdx.x * 4;
    *(__half2*)(rA + c)     = __half2(__float2half_rn(v[0]), __float2half_rn(v[1]));
    *(__half2*)(rA + c + 2) = __half2(__float2half_rn(v[2]), __float2half_rn(v[3]));
}

// ---------------------------------------------------------------------------
// K2: dist = g_A @ g_B^T via mma.sync fp16 (HMMA), K=512, plus per-tile row max.
// R9-validated config: 128x128 tile, BK=64, 3-stage cp.async ring,
// 8 warps (2M x 4N), warp 64x32, 2 CTAs/SM, plain stores.
// ---------------------------------------------------------------------------
#define BK       64
#define NITERS   (DIM / BK)            // 8
#define NSTAGES  3
#define ASTRIDE  72                    // fp16 elems per smem row (64 + 8 pad)
#define ATILE_B  (128 * ASTRIDE * 2)   // 18432 bytes
#define STAGE_B  (2 * ATILE_B)         // 36864 bytes (A + B)
#define SMEM_TOT (NSTAGES * STAGE_B)   // 110592 bytes

extern __shared__ char dyn_smem[];

__device__ __forceinline__ void load_tile(uint32_t sbase, int stage, int iter,
                                          int tid, int rowBase, int colBase) {
    int k0 = iter * BK;
    uint32_t st = sbase + stage * STAGE_B;
    #pragma unroll
    for (int i = 0; i < 8; i++) {
        int q = i * 256 + tid;            // 0..2047
        int isA = q < 1024;
        int qq = isA ? q : q - 1024;
        int row = qq >> 3;
        int seg = qq & 7;                 // 8 fp16 (16B) per seg
        const __half* src =
            (isA ? g_A + (size_t)(rowBase + row) * DIM
                 : g_B + (size_t)(colBase + row) * DIM) + k0 + seg * 8;
        uint32_t dst = st + (isA ? 0 : ATILE_B) + (row * ASTRIDE + seg * 8) * 2;
        cp16(dst, src);
    }
}

__global__ void __launch_bounds__(256, 2)
k_gemm_mma(float* __restrict__ dist) {
    __shared__ float s_rm[128][4];
    uint32_t sbase = smem_u32(dyn_smem);
    int tid  = threadIdx.x;
    int wid  = tid >> 5;
    int lane = tid & 31;
    int warpM = wid >> 2;      // 0..1  (64 rows each)
    int warpN = wid & 3;       // 0..3  (32 cols each)
    int rowBase = blockIdx.y * 128;
    int colBase = blockIdx.x * 128;

    float acc[4][4][4];
    #pragma unroll
    for (int mi = 0; mi < 4; mi++)
        #pragma unroll
        for (int ni = 0; ni < 4; ni++)
            #pragma unroll
            for (int r = 0; r < 4; r++) acc[mi][ni][r] = 0.0f;

    int amat = lane >> 3, ar = lane & 7;
    int arow_in = (amat & 1) * 8 + ar;
    int ak_in   = (amat >> 1) * 8;
    int ml = lane & 15;
    int brow_in = ml & 7;
    int bk_in   = (ml >> 3) * 8;

    load_tile(sbase, 0, 0, tid, rowBase, colBase);
    cp_commit();
    load_tile(sbase, 1, 1, tid, rowBase, colBase);
    cp_commit();

    for (int it = 0; it < NITERS; it++) {
        int stage = it % NSTAGES;
        cp_wait1();
        __syncthreads();
        if (it + 2 < NITERS)
            load_tile(sbase, (it + 2) % NSTAGES, it + 2, tid, rowBase, colBase);
        cp_commit();

        uint32_t sA = sbase + stage * STAGE_B;
        uint32_t sB = sA + ATILE_B;
        #pragma unroll
        for (int ks = 0; ks < 4; ks++) {
            uint32_t a0[4], a1[4], a2[4], a3[4];
            #pragma unroll
            for (int mi = 0; mi < 4; mi++) {
                uint32_t addr = sA +
                    ((warpM * 64 + mi * 16 + arow_in) * ASTRIDE + ks * 16 + ak_in) * 2;
                ldsm_x4(a0[mi], a1[mi], a2[mi], a3[mi], addr);
            }
            uint32_t b0[4], b1[4];
            #pragma unroll
            for (int ni = 0; ni < 4; ni++) {
                uint32_t addr = sB +
                    ((warpN * 32 + ni * 8 + brow_in) * ASTRIDE + ks * 16 + bk_in) * 2;
                ldsm_x2(b0[ni], b1[ni], addr);
            }
            #pragma unroll
            for (int mi = 0; mi < 4; mi++)
                #pragma unroll
                for (int ni = 0; ni < 4; ni++)
                    mma_fp16(acc[mi][ni][0], acc[mi][ni][1], acc[mi][ni][2], acc[mi][ni][3],
                             a0[mi], a1[mi], a2[mi], a3[mi], b0[ni], b1[ni]);
        }
    }

    // Epilogue: write dist + per-warp row maxes
    int g = lane >> 2;
    int cq = (lane & 3) * 2;
    #pragma unroll
    for (int mi = 0; mi < 4; mi++) {
        int r0 = rowBase + warpM * 64 + mi * 16 + g;
        float mlo = -INFINITY, mhi = -INFINITY;
        #pragma unroll
        for (int ni = 0; ni < 4; ni++) {
            int cc = colBase + warpN * 32 + ni * 8 + cq;
            *(float2*)(dist + (size_t)r0 * CODES + cc) =
                make_float2(acc[mi][ni][0], acc[mi][ni][1]);
            *(float2*)(dist + (size_t)(r0 + 8) * CODES + cc) =
                make_float2(acc[mi][ni][2], acc[mi][ni][3]);
            mlo = fmaxf(mlo, fmaxf(acc[mi][ni][0], acc[mi][ni][1]));
            mhi = fmaxf(mhi, fmaxf(acc[mi][ni][2], acc[mi][ni][3]));
        }
        #pragma unroll
        for (int o = 1; o < 4; o <<= 1) {
            mlo = fmaxf(mlo, __shfl_xor_sync(0xffffffffu, mlo, o));
            mhi = fmaxf(mhi, __shfl_xor_sync(0xffffffffu, mhi, o));
        }
        if ((lane & 3) == 0) {
            s_rm[warpM * 64 + mi * 16 + g][warpN]     = mlo;
            s_rm[warpM * 64 + mi * 16 + g + 8][warpN] = mhi;
        }
    }
    __syncthreads();
    if (tid < 128) {
        float m = fmaxf(fmaxf(s_rm[tid][0], s_rm[tid][1]),
                        fmaxf(s_rm[tid][2], s_rm[tid][3]));
        g_tilemax[(size_t)(rowBase + tid) * 64 + blockIdx.x] = m;
    }
}

// ---------------------------------------------------------------------------
// K3: candidate refinement + exact fp32 argmax (warp-parallel candidates)
//     + quantize gather + fused EMA scatter.
// One block (128 threads) per token row. 64 tiles of 128 cols.
// ---------------------------------------------------------------------------
__global__ void __launch_bounds__(128)
k_select(const float* __restrict__ dist, const float* __restrict__ embed,
         float* __restrict__ out_ind, float* __restrict__ out_q,
         float* __restrict__ out_cs, float* __restrict__ out_ea) {
    int t = blockIdx.x;
    int tid = threadIdx.x;
    int wid = tid >> 5, lane = tid & 31;

    __shared__ float s_tm[64];
    __shared__ float s_xs[DIM];
    __shared__ float s_M;
    __shared__ int   s_cand[64];
    __shared__ int   s_ncand;
    __shared__ float s_wbv[4];
    __shared__ int   s_wbi[4];
    __shared__ int   s_best;

    float4 xv = ((const float4*)(g_xn + (size_t)t * DIM))[tid];
    ((float4*)s_xs)[tid] = xv;
    if (tid < 64) s_tm[tid] = g_tilemax[(size_t)t * 64 + tid];
    if (tid == 0) s_ncand = 0;
    __syncthreads();
    if (tid < 32) {
        float m = fmaxf(s_tm[tid], s_tm[tid + 32]);
        #pragma unroll
        for (int o = 16; o > 0; o >>= 1) m = fmaxf(m, __shfl_xor_sync(0xffffffffu, m, o));
        if (tid == 0) s_M = m;
    }
    __syncthreads();
    float thr = s_M - MARGIN;
    const float* drow = dist + (size_t)t * CODES;
    for (int tile = 0; tile < 64; tile++) {
        if (s_tm[tile] > thr) {
            float v = drow[tile * 128 + tid];
            if (v > thr) {
                int p = atomicAdd(&s_ncand, 1);
                if (p < 64) s_cand[p] = tile * 128 + tid;
            }
        }
    }
    __syncthreads();
    int nc = min(s_ncand, 64);

    // Warp-parallel exact fp32 dots: warp w handles candidates w, w+4, ...
    float bestv = -INFINITY;
    int   besti = CODES;
    for (int ci = wid; ci < nc; ci += 4) {
        int c = s_cand[ci];
        const float4* ev4 = (const float4*)(embed + (size_t)c * DIM);
        float p = 0.0f;
        #pragma unroll
        for (int j = 0; j < 4; j++) {
            float4 e = ev4[lane * 4 + j];
            float4 xx = ((const float4*)s_xs)[lane * 4 + j];
            p += e.x * xx.x + e.y * xx.y + e.z * xx.z + e.w * xx.w;
        }
        #pragma unroll
        for (int o = 16; o > 0; o >>= 1) p += __shfl_xor_sync(0xffffffffu, p, o);
        if (p > bestv || (p == bestv && c < besti)) { bestv = p; besti = c; }
    }
    if (lane == 0) { s_wbv[wid] = bestv; s_wbi[wid] = besti; }
    __syncthreads();
    if (tid == 0) {
        float bv = s_wbv[0]; int bi = s_wbi[0];
        #pragma unroll
        for (int w = 1; w < 4; w++) {
            float v = s_wbv[w]; int i = s_wbi[w];
            if (v > bv || (v == bv && i < bi)) { bv = v; bi = i; }
        }
        g_ind[t] = bi;
        out_ind[t] = (float)bi;
        s_best = bi;
        atomicAdd(out_cs + bi, OMDF);
    }
    __syncthreads();
    int best = s_best;
    // quantize gather
    float4 ev = ((const float4*)(embed + (size_t)best * DIM))[tid];
    ((float4*)(out_q + (size_t)t * DIM))[tid] = ev;
    // fused EMA scatter: out_ea[best] += (1-decay) * xn
    float* er = out_ea + (size_t)best * DIM + tid * 4;
    atomicAdd(er + 0, OMDF * xv.x);
    atomicAdd(er + 1, OMDF * xv.y);
    atomicAdd(er + 2, OMDF * xv.z);
    atomicAdd(er + 3, OMDF * xv.w);
}

// ---------------------------------------------------------------------------
// K6: denom = sum(new_cluster_size)
// ---------------------------------------------------------------------------
__global__ void k_denom(const float* __restrict__ out_cs) {
    float s = 0.0f;
    for (int i = threadIdx.x; i < CODES; i += 1024) s += out_cs[i];
    #pragma unroll
    for (int o = 16; o > 0; o >>= 1) s += __shfl_xor_sync(0xffffffffu, s, o);
    __shared__ float ws[32];
    if ((threadIdx.x & 31) == 0) ws[threadIdx.x >> 5] = s;
    __syncthreads();
    if (threadIdx.x == 0) {
        float tot = 0.0f;
        for (int i = 0; i < 32; i++) tot += ws[i];
        g_denom = tot;
    }
}

// ---------------------------------------------------------------------------
// K7: new_embed = l2norm(new_embed_avg / smoothed)
// ---------------------------------------------------------------------------
__global__ void k_newembed(const float* __restrict__ out_cs,
                           const float* __restrict__ out_ea,
                           float* __restrict__ out_e) {
    int c = blockIdx.x;
    float denom = g_denom;
    float smoothed = (out_cs[c] + EPSF) / (denom + (float)CODES * EPSF) * denom;
    float invs = 1.0f / smoothed;
    float4 v = ((const float4*)(out_ea + (size_t)c * DIM))[threadIdx.x];
    float4 w = make_float4(v.x * invs, v.y * invs, v.z * invs, v.w * invs);
    float ss = w.x * w.x + w.y * w.y + w.z * w.z + w.w * w.w;
    #pragma unroll
    for (int o = 16; o > 0; o >>= 1) ss += __shfl_xor_sync(0xffffffffu, ss, o);
    __shared__ float warpsum[4];
    __shared__ float s_inv;
    if ((threadIdx.x & 31) == 0) warpsum[threadIdx.x >> 5] = ss;
    __syncthreads();
    if (threadIdx.x == 0) {
        float tot = warpsum[0] + warpsum[1] + warpsum[2] + warpsum[3];
        s_inv = 1.0f / fmaxf(sqrtf(tot), 1e-6f);
    }
    __syncthreads();
    float inv = s_inv;
    float4 o4 = make_float4(w.x * inv, w.y * inv, w.z * inv, w.w * inv);
    ((float4*)(out_e + (size_t)c * DIM))[threadIdx.x] = o4;
}

// ---------------------------------------------------------------------------
extern "C" void kernel_launch(void* const* d_in, const int* in_sizes, int n_in,
                              void* d_out, int out_size) {
    const float* x     = (const float*)d_in[0];
    const float* embed = (const float*)d_in[1];
    const float* cs    = (const float*)d_in[2];
    const float* ea    = (const float*)d_in[3];
    float* out = (float*)d_out;

    cudaFuncSetAttribute(k_gemm_mma, cudaFuncAttributeMaxDynamicSharedMemorySize,
                         SMEM_TOT);

    k_prep<<<TOKENS + CODES + EMA_BLOCKS, 128>>>(x, embed, cs, ea,
                                                 out + OFF_CS, out + OFF_EA);
    k_gemm_mma<<<dim3(CODES / 128, TOKENS / 128), 256, SMEM_TOT>>>(out + OFF_DIST);
    k_select<<<TOKENS, 128>>>(out + OFF_DIST, embed, out + OFF_IND, out + OFF_Q,
                              out + OFF_CS, out + OFF_EA);
    k_denom<<<1, 1024>>>(out + OFF_CS);
    k_newembed<<<CODES, 128>>>(out + OFF_CS, out + OFF_EA, out + OFF_E);
}

// round 15
// speedup vs baseline: 1.1440x; 1.0170x over previous
#include <cuda_runtime.h>
#include <cuda_fp16.h>
#include <cstdint>
#include <math.h>

// Problem constants
#define TOKENS 8192        // b*n = 4*2048
#define DIM    512
#define CODES  8192
#define DECAYF 0.8f
#define OMDF   (1.0f - 0.8f)
#define EPSF   1e-5f
#define MARGIN 3e-3f

// Output layout (floats), tuple order flattened
#define OFF_Q    ((size_t)0)
#define OFF_IND  ((size_t)4194304)
#define OFF_DIST ((size_t)4202496)
#define OFF_CS   ((size_t)71311360)
#define OFF_EA   ((size_t)71319552)
#define OFF_E    ((size_t)75513856)

// Scratch (device globals; no allocations allowed)
__device__ float g_xn[(size_t)TOKENS * DIM];   // l2-normalized x (fp32)
__device__ int   g_ind[TOKENS];
__device__ float g_denom;
__device__ float g_dsum = 0.0f;                // DECAY*sum(cs) accumulator
__device__ __half g_A[(size_t)TOKENS * DIM];   // fp16(xn)
__device__ __half g_B[(size_t)CODES  * DIM];   // fp16(embed)
__device__ float g_tilemax[(size_t)TOKENS * 64];  // per (row, 128-col tile) max

// ---------------------------------------------------------------------------
// helpers
// ---------------------------------------------------------------------------
__device__ __forceinline__ uint32_t smem_u32(const void* p) {
    uint32_t a;
    asm("{ .reg .u64 t; cvta.to.shared.u64 t, %1; cvt.u32.u64 %0, t; }" : "=r"(a) : "l"(p));
    return a;
}
__device__ __forceinline__ void cp16(uint32_t dst, const void* src) {
    asm volatile("cp.async.cg.shared.global [%0], [%1], 16;" :: "r"(dst), "l"(src));
}
__device__ __forceinline__ void cp_commit() {
    asm volatile("cp.async.commit_group;" ::: "memory");
}
__device__ __forceinline__ void cp_wait1() {
    asm volatile("cp.async.wait_group 1;" ::: "memory");
}
__device__ __forceinline__ void ldsm_x4(uint32_t& r0, uint32_t& r1, uint32_t& r2,
                                        uint32_t& r3, uint32_t addr) {
    asm volatile("ldmatrix.sync.aligned.m8n8.x4.shared.b16 {%0,%1,%2,%3}, [%4];"
                 : "=r"(r0), "=r"(r1), "=r"(r2), "=r"(r3) : "r"(addr));
}
__device__ __forceinline__ void ldsm_x2(uint32_t& r0, uint32_t& r1, uint32_t addr) {
    asm volatile("ldmatrix.sync.aligned.m8n8.x2.shared.b16 {%0,%1}, [%2];"
                 : "=r"(r0), "=r"(r1) : "r"(addr));
}
__device__ __forceinline__ void mma_fp16(float& c0, float& c1, float& c2, float& c3,
                                         uint32_t a0, uint32_t a1, uint32_t a2, uint32_t a3,
                                         uint32_t b0, uint32_t b1) {
    asm volatile(
        "mma.sync.aligned.m16n8k16.row.col.f32.f16.f16.f32 "
        "{%0,%1,%2,%3}, {%4,%5,%6,%7}, {%8,%9}, {%0,%1,%2,%3};"
        : "+f"(c0), "+f"(c1), "+f"(c2), "+f"(c3)
        : "r"(a0), "r"(a1), "r"(a2), "r"(a3), "r"(b0), "r"(b1));
}

// ---------------------------------------------------------------------------
// K1: fused prep. Blocks [0, TOKENS): l2-normalize x -> g_xn + g_A(fp16).
//     Blocks [TOKENS, TOKENS+CODES): g_B = fp16(embed).
// ---------------------------------------------------------------------------
__global__ void k_prep(const float* __restrict__ x, const float* __restrict__ embed) {
    int b = blockIdx.x;
    if (b >= TOKENS) {
        int c = b - TOKENS;
        float4 a = ((const float4*)(embed + (size_t)c * DIM))[threadIdx.x];
        __half* rB = g_B + (size_t)c * DIM;
        int d = threadIdx.x * 4;
        *(__half2*)(rB + d)     = __half2(__float2half_rn(a.x), __float2half_rn(a.y));
        *(__half2*)(rB + d + 2) = __half2(__float2half_rn(a.z), __float2half_rn(a.w));
        return;
    }
    int t = b;
    const float4* row = (const float4*)(x + (size_t)t * DIM);
    float4 a = row[threadIdx.x];                 // 128 threads * 4 = 512
    float ss = a.x * a.x + a.y * a.y + a.z * a.z + a.w * a.w;
    #pragma unroll
    for (int o = 16; o > 0; o >>= 1) ss += __shfl_xor_sync(0xffffffffu, ss, o);
    __shared__ float warpsum[4];
    __shared__ float s_inv;
    if ((threadIdx.x & 31) == 0) warpsum[threadIdx.x >> 5] = ss;
    __syncthreads();
    if (threadIdx.x == 0) {
        float tot = warpsum[0] + warpsum[1] + warpsum[2] + warpsum[3];
        s_inv = 1.0f / fmaxf(sqrtf(tot), 1e-6f);
    }
    __syncthreads();
    float inv = s_inv;
    float v[4] = {a.x * inv, a.y * inv, a.z * inv, a.w * inv};
    ((float4*)(g_xn + (size_t)t * DIM))[threadIdx.x] = make_float4(v[0], v[1], v[2], v[3]);
    __half* rA = g_A + (size_t)t * DIM;
    int c = threadIdx.x * 4;
    *(__half2*)(rA + c)     = __half2(__float2half_rn(v[0]), __float2half_rn(v[1]));
    *(__half2*)(rA + c + 2) = __half2(__float2half_rn(v[2]), __float2half_rn(v[3]));
}

// ---------------------------------------------------------------------------
// K1b: init EMA outputs with DECAY * old; also accumulate DECAY*sum(cs) into
//      g_dsum (g_dsum is 0 at entry each launch; k_select resets it).
// ---------------------------------------------------------------------------
__global__ void k_init_ema(const float* __restrict__ cs, const float* __restrict__ ea,
                           float* __restrict__ out_cs, float* __restrict__ out_ea) {
    size_t total = (size_t)CODES * DIM;
    float local = 0.0f;
    for (size_t i = blockIdx.x * (size_t)blockDim.x + threadIdx.x; i < total;
         i += (size_t)gridDim.x * blockDim.x) {
        out_ea[i] = DECAYF * ea[i];
        if (i < CODES) {
            float v = DECAYF * cs[i];
            out_cs[i] = v;
            local += v;
        }
    }
    #pragma unroll
    for (int o = 16; o > 0; o >>= 1) local += __shfl_xor_sync(0xffffffffu, local, o);
    if ((threadIdx.x & 31) == 0 && local != 0.0f) atomicAdd(&g_dsum, local);
}

// ---------------------------------------------------------------------------
// K2: dist = g_A @ g_B^T via mma.sync fp16 (HMMA), K=512, plus per-tile row max.
// R9-validated config: 128x128 tile, BK=64, 3-stage cp.async ring,
// 8 warps (2M x 4N), warp 64x32, 2 CTAs/SM, plain stores.
// ---------------------------------------------------------------------------
#define BK       64
#define NITERS   (DIM / BK)            // 8
#define NSTAGES  3
#define ASTRIDE  72                    // fp16 elems per smem row (64 + 8 pad)
#define ATILE_B  (128 * ASTRIDE * 2)   // 18432 bytes
#define STAGE_B  (2 * ATILE_B)         // 36864 bytes (A + B)
#define SMEM_TOT (NSTAGES * STAGE_B)   // 110592 bytes

extern __shared__ char dyn_smem[];

__device__ __forceinline__ void load_tile(uint32_t sbase, int stage, int iter,
                                          int tid, int rowBase, int colBase) {
    int k0 = iter * BK;
    uint32_t st = sbase + stage * STAGE_B;
    #pragma unroll
    for (int i = 0; i < 8; i++) {
        int q = i * 256 + tid;            // 0..2047
        int isA = q < 1024;
        int qq = isA ? q : q - 1024;
        int row = qq >> 3;
        int seg = qq & 7;                 // 8 fp16 (16B) per seg
        const __half* src =
            (isA ? g_A + (size_t)(rowBase + row) * DIM
                 : g_B + (size_t)(colBase + row) * DIM) + k0 + seg * 8;
        uint32_t dst = st + (isA ? 0 : ATILE_B) + (row * ASTRIDE + seg * 8) * 2;
        cp16(dst, src);
    }
}

__global__ void __launch_bounds__(256, 2)
k_gemm_mma(float* __restrict__ dist) {
    __shared__ float s_rm[128][4];
    uint32_t sbase = smem_u32(dyn_smem);
    int tid  = threadIdx.x;
    int wid  = tid >> 5;
    int lane = tid & 31;
    int warpM = wid >> 2;      // 0..1  (64 rows each)
    int warpN = wid & 3;       // 0..3  (32 cols each)
    int rowBase = blockIdx.y * 128;
    int colBase = blockIdx.x * 128;

    float acc[4][4][4];
    #pragma unroll
    for (int mi = 0; mi < 4; mi++)
        #pragma unroll
        for (int ni = 0; ni < 4; ni++)
            #pragma unroll
            for (int r = 0; r < 4; r++) acc[mi][ni][r] = 0.0f;

    int amat = lane >> 3, ar = lane & 7;
    int arow_in = (amat & 1) * 8 + ar;
    int ak_in   = (amat >> 1) * 8;
    int ml = lane & 15;
    int brow_in = ml & 7;
    int bk_in   = (ml >> 3) * 8;

    load_tile(sbase, 0, 0, tid, rowBase, colBase);
    cp_commit();
    load_tile(sbase, 1, 1, tid, rowBase, colBase);
    cp_commit();

    for (int it = 0; it < NITERS; it++) {
        int stage = it % NSTAGES;
        cp_wait1();
        __syncthreads();
        if (it + 2 < NITERS)
            load_tile(sbase, (it + 2) % NSTAGES, it + 2, tid, rowBase, colBase);
        cp_commit();

        uint32_t sA = sbase + stage * STAGE_B;
        uint32_t sB = sA + ATILE_B;
        #pragma unroll
        for (int ks = 0; ks < 4; ks++) {
            uint32_t a0[4], a1[4], a2[4], a3[4];
            #pragma unroll
            for (int mi = 0; mi < 4; mi++) {
                uint32_t addr = sA +
                    ((warpM * 64 + mi * 16 + arow_in) * ASTRIDE + ks * 16 + ak_in) * 2;
                ldsm_x4(a0[mi], a1[mi], a2[mi], a3[mi], addr);
            }
            uint32_t b0[4], b1[4];
            #pragma unroll
            for (int ni = 0; ni < 4; ni++) {
                uint32_t addr = sB +
                    ((warpN * 32 + ni * 8 + brow_in) * ASTRIDE + ks * 16 + bk_in) * 2;
                ldsm_x2(b0[ni], b1[ni], addr);
            }
            #pragma unroll
            for (int mi = 0; mi < 4; mi++)
                #pragma unroll
                for (int ni = 0; ni < 4; ni++)
                    mma_fp16(acc[mi][ni][0], acc[mi][ni][1], acc[mi][ni][2], acc[mi][ni][3],
                             a0[mi], a1[mi], a2[mi], a3[mi], b0[ni], b1[ni]);
        }
    }

    // Epilogue: write dist + per-warp row maxes
    int g = lane >> 2;
    int cq = (lane & 3) * 2;
    #pragma unroll
    for (int mi = 0; mi < 4; mi++) {
        int r0 = rowBase + warpM * 64 + mi * 16 + g;
        float mlo = -INFINITY, mhi = -INFINITY;
        #pragma unroll
        for (int ni = 0; ni < 4; ni++) {
            int cc = colBase + warpN * 32 + ni * 8 + cq;
            *(float2*)(dist + (size_t)r0 * CODES + cc) =
                make_float2(acc[mi][ni][0], acc[mi][ni][1]);
            *(float2*)(dist + (size_t)(r0 + 8) * CODES + cc) =
                make_float2(acc[mi][ni][2], acc[mi][ni][3]);
            mlo = fmaxf(mlo, fmaxf(acc[mi][ni][0], acc[mi][ni][1]));
            mhi = fmaxf(mhi, fmaxf(acc[mi][ni][2], acc[mi][ni][3]));
        }
        #pragma unroll
        for (int o = 1; o < 4; o <<= 1) {
            mlo = fmaxf(mlo, __shfl_xor_sync(0xffffffffu, mlo, o));
            mhi = fmaxf(mhi, __shfl_xor_sync(0xffffffffu, mhi, o));
        }
        if ((lane & 3) == 0) {
            s_rm[warpM * 64 + mi * 16 + g][warpN]     = mlo;
            s_rm[warpM * 64 + mi * 16 + g + 8][warpN] = mhi;
        }
    }
    __syncthreads();
    if (tid < 128) {
        float m = fmaxf(fmaxf(s_rm[tid][0], s_rm[tid][1]),
                        fmaxf(s_rm[tid][2], s_rm[tid][3]));
        g_tilemax[(size_t)(rowBase + tid) * 64 + blockIdx.x] = m;
    }
}

// ---------------------------------------------------------------------------
// K3: per-row candidate refinement + exact fp32 argmax + quantize gather
//     + fused EMA scatter. Block 0 also publishes denom and resets g_dsum.
// One block (128 threads) per token row. 64 tiles of 128 cols.
// ---------------------------------------------------------------------------
__global__ void __launch_bounds__(128)
k_select(const float* __restrict__ dist, const float* __restrict__ embed,
         float* __restrict__ out_ind, float* __restrict__ out_q,
         float* __restrict__ out_cs, float* __restrict__ out_ea) {
    int t = blockIdx.x;
    int tid = threadIdx.x;
    int wid = tid >> 5, lane = tid & 31;

    if (t == 0 && tid == 0) {
        // All k_init_ema atomics completed (kernel-boundary ordering).
        g_denom = g_dsum + OMDF * (float)TOKENS;
        g_dsum = 0.0f;   // restore invariant for next launch/replay
    }

    __shared__ float s_tm[64];
    __shared__ float s_M;
    __shared__ int   s_cand[64];
    __shared__ int   s_ncand;
    __shared__ float s_red[4];
    __shared__ int   s_best;

    if (tid < 64) s_tm[tid] = g_tilemax[(size_t)t * 64 + tid];
    if (tid == 0) s_ncand = 0;
    __syncthreads();
    if (tid < 32) {
        float m = fmaxf(s_tm[tid], s_tm[tid + 32]);
        #pragma unroll
        for (int o = 16; o > 0; o >>= 1) m = fmaxf(m, __shfl_xor_sync(0xffffffffu, m, o));
        if (tid == 0) s_M = m;
    }
    __syncthreads();
    float thr = s_M - MARGIN;
    const float* drow = dist + (size_t)t * CODES;
    for (int tile = 0; tile < 64; tile++) {
        if (s_tm[tile] > thr) {
            float v = drow[tile * 128 + tid];
            if (v > thr) {
                int p = atomicAdd(&s_ncand, 1);
                if (p < 64) s_cand[p] = tile * 128 + tid;
            }
        }
    }
    __syncthreads();
    int nc = min(s_ncand, 64);

    float4 xv = ((const float4*)(g_xn + (size_t)t * DIM))[tid];
    float bestv = -INFINITY;
    int   besti = CODES;
    for (int ci = 0; ci < nc; ci++) {
        int c = s_cand[ci];
        float4 ev = ((const float4*)(embed + (size_t)c * DIM))[tid];
        float p = xv.x * ev.x + xv.y * ev.y + xv.z * ev.z + xv.w * ev.w;
        #pragma unroll
        for (int o = 16; o > 0; o >>= 1) p += __shfl_xor_sync(0xffffffffu, p, o);
        if (lane == 0) s_red[wid] = p;
        __syncthreads();
        if (tid == 0) {
            float d = (s_red[0] + s_red[1]) + (s_red[2] + s_red[3]);
            if (d > bestv || (d == bestv && c < besti)) { bestv = d; besti = c; }
        }
        __syncthreads();
    }
    if (tid == 0) {
        g_ind[t] = besti;
        out_ind[t] = (float)besti;
        s_best = besti;
        atomicAdd(out_cs + besti, OMDF);
    }
    __syncthreads();
    int best = s_best;
    // quantize gather
    float4 ev = ((const float4*)(embed + (size_t)best * DIM))[tid];
    ((float4*)(out_q + (size_t)t * DIM))[tid] = ev;
    // fused EMA scatter: out_ea[best] += (1-decay) * xn
    float* er = out_ea + (size_t)best * DIM + tid * 4;
    atomicAdd(er + 0, OMDF * xv.x);
    atomicAdd(er + 1, OMDF * xv.y);
    atomicAdd(er + 2, OMDF * xv.z);
    atomicAdd(er + 3, OMDF * xv.w);
}

// ---------------------------------------------------------------------------
// K7: new_embed = l2norm(new_embed_avg / smoothed)
// ---------------------------------------------------------------------------
__global__ void k_newembed(const float* __restrict__ out_cs,
                           const float* __restrict__ out_ea,
                           float* __restrict__ out_e) {
    int c = blockIdx.x;
    float denom = g_denom;
    float smoothed = (out_cs[c] + EPSF) / (denom + (float)CODES * EPSF) * denom;
    float invs = 1.0f / smoothed;
    float4 v = ((const float4*)(out_ea + (size_t)c * DIM))[threadIdx.x];
    float4 w = make_float4(v.x * invs, v.y * invs, v.z * invs, v.w * invs);
    float ss = w.x * w.x + w.y * w.y + w.z * w.z + w.w * w.w;
    #pragma unroll
    for (int o = 16; o > 0; o >>= 1) ss += __shfl_xor_sync(0xffffffffu, ss, o);
    __shared__ float warpsum[4];
    __shared__ float s_inv;
    if ((threadIdx.x & 31) == 0) warpsum[threadIdx.x >> 5] = ss;
    __syncthreads();
    if (threadIdx.x == 0) {
        float tot = warpsum[0] + warpsum[1] + warpsum[2] + warpsum[3];
        s_inv = 1.0f / fmaxf(sqrtf(tot), 1e-6f);
    }
    __syncthreads();
    float inv = s_inv;
    float4 o4 = make_float4(w.x * inv, w.y * inv, w.z * inv, w.w * inv);
    ((float4*)(out_e + (size_t)c * DIM))[threadIdx.x] = o4;
}

// ---------------------------------------------------------------------------
extern "C" void kernel_launch(void* const* d_in, const int* in_sizes, int n_in,
                              void* d_out, int out_size) {
    const float* x     = (const float*)d_in[0];
    const float* embed = (const float*)d_in[1];
    const float* cs    = (const float*)d_in[2];
    const float* ea    = (const float*)d_in[3];
    float* out = (float*)d_out;

    cudaFuncSetAttribute(k_gemm_mma, cudaFuncAttributeMaxDynamicSharedMemorySize,
                         SMEM_TOT);

    k_prep<<<TOKENS + CODES, 128>>>(x, embed);
    k_init_ema<<<2048, 256>>>(cs, ea, out + OFF_CS, out + OFF_EA);
    k_gemm_mma<<<dim3(CODES / 128, TOKENS / 128), 256, SMEM_TOT>>>(out + OFF_DIST);
    k_select<<<TOKENS, 128>>>(out + OFF_DIST, embed, out + OFF_IND, out + OFF_Q,
                              out + OFF_CS, out + OFF_EA);
    k_newembed<<<CODES, 128>>>(out + OFF_CS, out + OFF_EA, out + OFF_E);
}

// round 16
// speedup vs baseline: 1.1610x; 1.0149x over previous
#include <cuda_runtime.h>
#include <cuda_fp16.h>
#include <cstdint>
#include <math.h>

// Problem constants
#define TOKENS 8192        // b*n = 4*2048
#define DIM    512
#define CODES  8192
#define DECAYF 0.8f
#define OMDF   (1.0f - 0.8f)
#define EPSF   1e-5f
#define MARGIN 3e-3f

// Output layout (floats), tuple order flattened
#define OFF_Q    ((size_t)0)
#define OFF_IND  ((size_t)4194304)
#define OFF_DIST ((size_t)4202496)
#define OFF_CS   ((size_t)71311360)
#define OFF_EA   ((size_t)71319552)
#define OFF_E    ((size_t)75513856)

// Scratch (device globals; no allocations allowed)
__device__ float g_xn[(size_t)TOKENS * DIM];   // l2-normalized x (fp32)
__device__ int   g_ind[TOKENS];
__device__ float g_denom;
__device__ float g_dsum = 0.0f;                // DECAY*sum(cs) accumulator
__device__ __half g_A[(size_t)TOKENS * DIM];   // fp16(xn)
__device__ __half g_B[(size_t)CODES  * DIM];   // fp16(embed)
__device__ float g_tilemax[(size_t)TOKENS * 64];  // per (row, 128-col tile) max

// ---------------------------------------------------------------------------
// helpers
// ---------------------------------------------------------------------------
__device__ __forceinline__ uint32_t smem_u32(const void* p) {
    uint32_t a;
    asm("{ .reg .u64 t; cvta.to.shared.u64 t, %1; cvt.u32.u64 %0, t; }" : "=r"(a) : "l"(p));
    return a;
}
__device__ __forceinline__ void cp16(uint32_t dst, const void* src) {
    asm volatile("cp.async.cg.shared.global [%0], [%1], 16;" :: "r"(dst), "l"(src));
}
__device__ __forceinline__ void cp_commit() {
    asm volatile("cp.async.commit_group;" ::: "memory");
}
__device__ __forceinline__ void cp_wait1() {
    asm volatile("cp.async.wait_group 1;" ::: "memory");
}
__device__ __forceinline__ void ldsm_x4(uint32_t& r0, uint32_t& r1, uint32_t& r2,
                                        uint32_t& r3, uint32_t addr) {
    asm volatile("ldmatrix.sync.aligned.m8n8.x4.shared.b16 {%0,%1,%2,%3}, [%4];"
                 : "=r"(r0), "=r"(r1), "=r"(r2), "=r"(r3) : "r"(addr));
}
__device__ __forceinline__ void ldsm_x2(uint32_t& r0, uint32_t& r1, uint32_t addr) {
    asm volatile("ldmatrix.sync.aligned.m8n8.x2.shared.b16 {%0,%1}, [%2];"
                 : "=r"(r0), "=r"(r1) : "r"(addr));
}
__device__ __forceinline__ void mma_fp16(float& c0, float& c1, float& c2, float& c3,
                                         uint32_t a0, uint32_t a1, uint32_t a2, uint32_t a3,
                                         uint32_t b0, uint32_t b1) {
    asm volatile(
        "mma.sync.aligned.m16n8k16.row.col.f32.f16.f16.f32 "
        "{%0,%1,%2,%3}, {%4,%5,%6,%7}, {%8,%9}, {%0,%1,%2,%3};"
        : "+f"(c0), "+f"(c1), "+f"(c2), "+f"(c3)
        : "r"(a0), "r"(a1), "r"(a2), "r"(a3), "r"(b0), "r"(b1));
}

// ---------------------------------------------------------------------------
// K1: fused prep. Blocks [0, TOKENS): l2-normalize x -> g_xn + g_A(fp16).
//     Blocks [TOKENS, TOKENS+CODES): g_B = fp16(embed).
// ---------------------------------------------------------------------------
__global__ void k_prep(const float* __restrict__ x, const float* __restrict__ embed) {
    int b = blockIdx.x;
    if (b >= TOKENS) {
        int c = b - TOKENS;
        float4 a = ((const float4*)(embed + (size_t)c * DIM))[threadIdx.x];
        __half* rB = g_B + (size_t)c * DIM;
        int d = threadIdx.x * 4;
        *(__half2*)(rB + d)     = __half2(__float2half_rn(a.x), __float2half_rn(a.y));
        *(__half2*)(rB + d + 2) = __half2(__float2half_rn(a.z), __float2half_rn(a.w));
        return;
    }
    int t = b;
    const float4* row = (const float4*)(x + (size_t)t * DIM);
    float4 a = row[threadIdx.x];                 // 128 threads * 4 = 512
    float ss = a.x * a.x + a.y * a.y + a.z * a.z + a.w * a.w;
    #pragma unroll
    for (int o = 16; o > 0; o >>= 1) ss += __shfl_xor_sync(0xffffffffu, ss, o);
    __shared__ float warpsum[4];
    __shared__ float s_inv;
    if ((threadIdx.x & 31) == 0) warpsum[threadIdx.x >> 5] = ss;
    __syncthreads();
    if (threadIdx.x == 0) {
        float tot = warpsum[0] + warpsum[1] + warpsum[2] + warpsum[3];
        s_inv = 1.0f / fmaxf(sqrtf(tot), 1e-6f);
    }
    __syncthreads();
    float inv = s_inv;
    float v[4] = {a.x * inv, a.y * inv, a.z * inv, a.w * inv};
    ((float4*)(g_xn + (size_t)t * DIM))[threadIdx.x] = make_float4(v[0], v[1], v[2], v[3]);
    __half* rA = g_A + (size_t)t * DIM;
    int c = threadIdx.x * 4;
    *(__half2*)(rA + c)     = __half2(__float2half_rn(v[0]), __float2half_rn(v[1]));
    *(__half2*)(rA + c + 2) = __half2(__float2half_rn(v[2]), __float2half_rn(v[3]));
}

// ---------------------------------------------------------------------------
// K2: dist = g_A @ g_B^T via mma.sync fp16 (HMMA), K=512, plus per-tile row max.
// R9-validated config: 128x128 tile, BK=64, 3-stage cp.async ring,
// 8 warps (2M x 4N), warp 64x32, 2 CTAs/SM, plain stores.
// Extra CTA row (blockIdx.y == 64): EMA decay-init (overlapped with GEMM wave 1):
//   out_ea = decay*ea; out_cs = decay*cs; g_dsum += decay*sum(cs).
// ---------------------------------------------------------------------------
#define BK       64
#define NITERS   (DIM / BK)            // 8
#define NSTAGES  3
#define ASTRIDE  72                    // fp16 elems per smem row (64 + 8 pad)
#define ATILE_B  (128 * ASTRIDE * 2)   // 18432 bytes
#define STAGE_B  (2 * ATILE_B)         // 36864 bytes (A + B)
#define SMEM_TOT (NSTAGES * STAGE_B)   // 110592 bytes

extern __shared__ char dyn_smem[];

__device__ __forceinline__ void load_tile(uint32_t sbase, int stage, int iter,
                                          int tid, int rowBase, int colBase) {
    int k0 = iter * BK;
    uint32_t st = sbase + stage * STAGE_B;
    #pragma unroll
    for (int i = 0; i < 8; i++) {
        int q = i * 256 + tid;            // 0..2047
        int isA = q < 1024;
        int qq = isA ? q : q - 1024;
        int row = qq >> 3;
        int seg = qq & 7;                 // 8 fp16 (16B) per seg
        const __half* src =
            (isA ? g_A + (size_t)(rowBase + row) * DIM
                 : g_B + (size_t)(colBase + row) * DIM) + k0 + seg * 8;
        uint32_t dst = st + (isA ? 0 : ATILE_B) + (row * ASTRIDE + seg * 8) * 2;
        cp16(dst, src);
    }
}

__global__ void __launch_bounds__(256, 2)
k_gemm_mma(float* __restrict__ dist,
           const float* __restrict__ cs, const float* __restrict__ ea,
           float* __restrict__ out_cs, float* __restrict__ out_ea) {
    int tid  = threadIdx.x;

    // ---- EMA init CTAs (wave-1 overlap) ----
    if (blockIdx.y == 64) {
        int gid = blockIdx.x * 256 + tid;            // 0..16383
        const float4* ea4 = (const float4*)ea;
        float4* oea4 = (float4*)out_ea;
        for (int i = gid; i < CODES * DIM / 4; i += 64 * 256) {
            float4 v = ea4[i];
            oea4[i] = make_float4(DECAYF * v.x, DECAYF * v.y, DECAYF * v.z, DECAYF * v.w);
        }
        float local = 0.0f;
        if (gid < CODES / 4) {
            float4 v = ((const float4*)cs)[gid];
            float4 w = make_float4(DECAYF * v.x, DECAYF * v.y, DECAYF * v.z, DECAYF * v.w);
            ((float4*)out_cs)[gid] = w;
            local = w.x + w.y + w.z + w.w;
        }
        #pragma unroll
        for (int o = 16; o > 0; o >>= 1) local += __shfl_xor_sync(0xffffffffu, local, o);
        if ((tid & 31) == 0 && local != 0.0f) atomicAdd(&g_dsum, local);
        return;
    }

    __shared__ float s_rm[128][4];
    uint32_t sbase = smem_u32(dyn_smem);
    int wid  = tid >> 5;
    int lane = tid & 31;
    int warpM = wid >> 2;      // 0..1  (64 rows each)
    int warpN = wid & 3;       // 0..3  (32 cols each)
    int rowBase = blockIdx.y * 128;
    int colBase = blockIdx.x * 128;

    float acc[4][4][4];
    #pragma unroll
    for (int mi = 0; mi < 4; mi++)
        #pragma unroll
        for (int ni = 0; ni < 4; ni++)
            #pragma unroll
            for (int r = 0; r < 4; r++) acc[mi][ni][r] = 0.0f;

    int amat = lane >> 3, ar = lane & 7;
    int arow_in = (amat & 1) * 8 + ar;
    int ak_in   = (amat >> 1) * 8;
    int ml = lane & 15;
    int brow_in = ml & 7;
    int bk_in   = (ml >> 3) * 8;

    load_tile(sbase, 0, 0, tid, rowBase, colBase);
    cp_commit();
    load_tile(sbase, 1, 1, tid, rowBase, colBase);
    cp_commit();

    for (int it = 0; it < NITERS; it++) {
        int stage = it % NSTAGES;
        cp_wait1();
        __syncthreads();
        if (it + 2 < NITERS)
            load_tile(sbase, (it + 2) % NSTAGES, it + 2, tid, rowBase, colBase);
        cp_commit();

        uint32_t sA = sbase + stage * STAGE_B;
        uint32_t sB = sA + ATILE_B;
        #pragma unroll
        for (int ks = 0; ks < 4; ks++) {
            uint32_t a0[4], a1[4], a2[4], a3[4];
            #pragma unroll
            for (int mi = 0; mi < 4; mi++) {
                uint32_t addr = sA +
                    ((warpM * 64 + mi * 16 + arow_in) * ASTRIDE + ks * 16 + ak_in) * 2;
                ldsm_x4(a0[mi], a1[mi], a2[mi], a3[mi], addr);
            }
            uint32_t b0[4], b1[4];
            #pragma unroll
            for (int ni = 0; ni < 4; ni++) {
                uint32_t addr = sB +
                    ((warpN * 32 + ni * 8 + brow_in) * ASTRIDE + ks * 16 + bk_in) * 2;
                ldsm_x2(b0[ni], b1[ni], addr);
            }
            #pragma unroll
            for (int mi = 0; mi < 4; mi++)
                #pragma unroll
                for (int ni = 0; ni < 4; ni++)
                    mma_fp16(acc[mi][ni][0], acc[mi][ni][1], acc[mi][ni][2], acc[mi][ni][3],
                             a0[mi], a1[mi], a2[mi], a3[mi], b0[ni], b1[ni]);
        }
    }

    // Epilogue: write dist + per-warp row maxes
    int g = lane >> 2;
    int cq = (lane & 3) * 2;
    #pragma unroll
    for (int mi = 0; mi < 4; mi++) {
        int r0 = rowBase + warpM * 64 + mi * 16 + g;
        float mlo = -INFINITY, mhi = -INFINITY;
        #pragma unroll
        for (int ni = 0; ni < 4; ni++) {
            int cc = colBase + warpN * 32 + ni * 8 + cq;
            *(float2*)(dist + (size_t)r0 * CODES + cc) =
                make_float2(acc[mi][ni][0], acc[mi][ni][1]);
            *(float2*)(dist + (size_t)(r0 + 8) * CODES + cc) =
                make_float2(acc[mi][ni][2], acc[mi][ni][3]);
            mlo = fmaxf(mlo, fmaxf(acc[mi][ni][0], acc[mi][ni][1]));
            mhi = fmaxf(mhi, fmaxf(acc[mi][ni][2], acc[mi][ni][3]));
        }
        #pragma unroll
        for (int o = 1; o < 4; o <<= 1) {
            mlo = fmaxf(mlo, __shfl_xor_sync(0xffffffffu, mlo, o));
            mhi = fmaxf(mhi, __shfl_xor_sync(0xffffffffu, mhi, o));
        }
        if ((lane & 3) == 0) {
            s_rm[warpM * 64 + mi * 16 + g][warpN]     = mlo;
            s_rm[warpM * 64 + mi * 16 + g + 8][warpN] = mhi;
        }
    }
    __syncthreads();
    if (tid < 128) {
        float m = fmaxf(fmaxf(s_rm[tid][0], s_rm[tid][1]),
                        fmaxf(s_rm[tid][2], s_rm[tid][3]));
        g_tilemax[(size_t)(rowBase + tid) * 64 + blockIdx.x] = m;
    }
}

// ---------------------------------------------------------------------------
// K3: per-row candidate refinement + exact fp32 argmax + quantize gather
//     + fused EMA scatter. Block 0 also publishes denom and resets g_dsum.
// One block (128 threads) per token row. 64 tiles of 128 cols.
// ---------------------------------------------------------------------------
__global__ void __launch_bounds__(128)
k_select(const float* __restrict__ dist, const float* __restrict__ embed,
         float* __restrict__ out_ind, float* __restrict__ out_q,
         float* __restrict__ out_cs, float* __restrict__ out_ea) {
    int t = blockIdx.x;
    int tid = threadIdx.x;
    int wid = tid >> 5, lane = tid & 31;

    if (t == 0 && tid == 0) {
        // All k_gemm_mma (incl. EMA-init CTAs) atomics completed.
        g_denom = g_dsum + OMDF * (float)TOKENS;
        g_dsum = 0.0f;   // restore invariant for next launch/replay
    }

    __shared__ float s_tm[64];
    __shared__ float s_M;
    __shared__ int   s_cand[64];
    __shared__ int   s_ncand;
    __shared__ float s_red[4];
    __shared__ int   s_best;

    if (tid < 64) s_tm[tid] = g_tilemax[(size_t)t * 64 + tid];
    if (tid == 0) s_ncand = 0;
    __syncthreads();
    if (tid < 32) {
        float m = fmaxf(s_tm[tid], s_tm[tid + 32]);
        #pragma unroll
        for (int o = 16; o > 0; o >>= 1) m = fmaxf(m, __shfl_xor_sync(0xffffffffu, m, o));
        if (tid == 0) s_M = m;
    }
    __syncthreads();
    float thr = s_M - MARGIN;
    const float* drow = dist + (size_t)t * CODES;
    for (int tile = 0; tile < 64; tile++) {
        if (s_tm[tile] > thr) {
            float v = drow[tile * 128 + tid];
            if (v > thr) {
                int p = atomicAdd(&s_ncand, 1);
                if (p < 64) s_cand[p] = tile * 128 + tid;
            }
        }
    }
    __syncthreads();
    int nc = min(s_ncand, 64);

    float4 xv = ((const float4*)(g_xn + (size_t)t * DIM))[tid];
    float bestv = -INFINITY;
    int   besti = CODES;
    for (int ci = 0; ci < nc; ci++) {
        int c = s_cand[ci];
        float4 ev = ((const float4*)(embed + (size_t)c * DIM))[tid];
        float p = xv.x * ev.x + xv.y * ev.y + xv.z * ev.z + xv.w * ev.w;
        #pragma unroll
        for (int o = 16; o > 0; o >>= 1) p += __shfl_xor_sync(0xffffffffu, p, o);
        if (lane == 0) s_red[wid] = p;
        __syncthreads();
        if (tid == 0) {
            float d = (s_red[0] + s_red[1]) + (s_red[2] + s_red[3]);
            if (d > bestv || (d == bestv && c < besti)) { bestv = d; besti = c; }
        }
        __syncthreads();
    }
    if (tid == 0) {
        g_ind[t] = besti;
        out_ind[t] = (float)besti;
        s_best = besti;
        atomicAdd(out_cs + besti, OMDF);
    }
    __syncthreads();
    int best = s_best;
    // quantize gather
    float4 ev = ((const float4*)(embed + (size_t)best * DIM))[tid];
    ((float4*)(out_q + (size_t)t * DIM))[tid] = ev;
    // fused EMA scatter: out_ea[best] += (1-decay) * xn
    float* er = out_ea + (size_t)best * DIM + tid * 4;
    atomicAdd(er + 0, OMDF * xv.x);
    atomicAdd(er + 1, OMDF * xv.y);
    atomicAdd(er + 2, OMDF * xv.z);
    atomicAdd(er + 3, OMDF * xv.w);
}

// ---------------------------------------------------------------------------
// K7: new_embed = l2norm(new_embed_avg / smoothed)
// ---------------------------------------------------------------------------
__global__ void k_newembed(const float* __restrict__ out_cs,
                           const float* __restrict__ out_ea,
                           float* __restrict__ out_e) {
    int c = blockIdx.x;
    float denom = g_denom;
    float smoothed = (out_cs[c] + EPSF) / (denom + (float)CODES * EPSF) * denom;
    float invs = 1.0f / smoothed;
    float4 v = ((const float4*)(out_ea + (size_t)c * DIM))[threadIdx.x];
    float4 w = make_float4(v.x * invs, v.y * invs, v.z * invs, v.w * invs);
    float ss = w.x * w.x + w.y * w.y + w.z * w.z + w.w * w.w;
    #pragma unroll
    for (int o = 16; o > 0; o >>= 1) ss += __shfl_xor_sync(0xffffffffu, ss, o);
    __shared__ float warpsum[4];
    __shared__ float s_inv;
    if ((threadIdx.x & 31) == 0) warpsum[threadIdx.x >> 5] = ss;
    __syncthreads();
    if (threadIdx.x == 0) {
        float tot = warpsum[0] + warpsum[1] + warpsum[2] + warpsum[3];
        s_inv = 1.0f / fmaxf(sqrtf(tot), 1e-6f);
    }
    __syncthreads();
    float inv = s_inv;
    float4 o4 = make_float4(w.x * inv, w.y * inv, w.z * inv, w.w * inv);
    ((float4*)(out_e + (size_t)c * DIM))[threadIdx.x] = o4;
}

// ---------------------------------------------------------------------------
extern "C" void kernel_launch(void* const* d_in, const int* in_sizes, int n_in,
                              void* d_out, int out_size) {
    const float* x     = (const float*)d_in[0];
    const float* embed = (const float*)d_in[1];
    const float* cs    = (const float*)d_in[2];
    const float* ea    = (const float*)d_in[3];
    float* out = (float*)d_out;

    cudaFuncSetAttribute(k_gemm_mma, cudaFuncAttributeMaxDynamicSharedMemorySize,
                         SMEM_TOT);

    k_prep<<<TOKENS + CODES, 128>>>(x, embed);
    k_gemm_mma<<<dim3(CODES / 128, TOKENS / 128 + 1), 256, SMEM_TOT>>>(
        out + OFF_DIST, cs, ea, out + OFF_CS, out + OFF_EA);
    k_select<<<TOKENS, 128>>>(out + OFF_DIST, embed, out + OFF_IND, out + OFF_Q,
                              out + OFF_CS, out + OFF_EA);
    k_newembed<<<CODES, 128>>>(out + OFF_CS, out + OFF_EA, out + OFF_E);
}

// round 17
// speedup vs baseline: 1.1861x; 1.0216x over previous
#include <cuda_runtime.h>
#include <cuda_fp16.h>
#include <cstdint>
#include <math.h>

// Problem constants
#define TOKENS 8192        // b*n = 4*2048
#define DIM    512
#define CODES  8192
#define DECAYF 0.8f
#define OMDF   (1.0f - 0.8f)
#define EPSF   1e-5f
#define MARGIN 3e-3f

// Output layout (floats), tuple order flattened
#define OFF_Q    ((size_t)0)
#define OFF_IND  ((size_t)4194304)
#define OFF_DIST ((size_t)4202496)
#define OFF_CS   ((size_t)71311360)
#define OFF_EA   ((size_t)71319552)
#define OFF_E    ((size_t)75513856)

// Scratch (device globals; no allocations allowed)
__device__ float g_xn[(size_t)TOKENS * DIM];   // l2-normalized x (fp32)
__device__ int   g_ind[TOKENS];
__device__ float g_denom;
__device__ float g_dsum = 0.0f;                // DECAY*sum(cs) accumulator
__device__ __half g_A[(size_t)TOKENS * DIM];   // fp16(xn)
__device__ __half g_B[(size_t)CODES  * DIM];   // fp16(embed)
__device__ float g_tilemax[(size_t)TOKENS * 64];  // per (row, 128-col tile) max

// ---------------------------------------------------------------------------
// helpers
// ---------------------------------------------------------------------------
__device__ __forceinline__ uint32_t smem_u32(const void* p) {
    uint32_t a;
    asm("{ .reg .u64 t; cvta.to.shared.u64 t, %1; cvt.u32.u64 %0, t; }" : "=r"(a) : "l"(p));
    return a;
}
__device__ __forceinline__ void cp16(uint32_t dst, const void* src) {
    asm volatile("cp.async.cg.shared.global [%0], [%1], 16;" :: "r"(dst), "l"(src));
}
__device__ __forceinline__ void cp_commit() {
    asm volatile("cp.async.commit_group;" ::: "memory");
}
__device__ __forceinline__ void cp_wait1() {
    asm volatile("cp.async.wait_group 1;" ::: "memory");
}
__device__ __forceinline__ void ldsm_x4(uint32_t& r0, uint32_t& r1, uint32_t& r2,
                                        uint32_t& r3, uint32_t addr) {
    asm volatile("ldmatrix.sync.aligned.m8n8.x4.shared.b16 {%0,%1,%2,%3}, [%4];"
                 : "=r"(r0), "=r"(r1), "=r"(r2), "=r"(r3) : "r"(addr));
}
__device__ __forceinline__ void ldsm_x2(uint32_t& r0, uint32_t& r1, uint32_t addr) {
    asm volatile("ldmatrix.sync.aligned.m8n8.x2.shared.b16 {%0,%1}, [%2];"
                 : "=r"(r0), "=r"(r1) : "r"(addr));
}
__device__ __forceinline__ void mma_fp16(float& c0, float& c1, float& c2, float& c3,
                                         uint32_t a0, uint32_t a1, uint32_t a2, uint32_t a3,
                                         uint32_t b0, uint32_t b1) {
    asm volatile(
        "mma.sync.aligned.m16n8k16.row.col.f32.f16.f16.f32 "
        "{%0,%1,%2,%3}, {%4,%5,%6,%7}, {%8,%9}, {%0,%1,%2,%3};"
        : "+f"(c0), "+f"(c1), "+f"(c2), "+f"(c3)
        : "r"(a0), "r"(a1), "r"(a2), "r"(a3), "r"(b0), "r"(b1));
}

// ---------------------------------------------------------------------------
// K1: fused prep, one WARP per row (no block barriers).
//   blocks [0, TOKENS/8):            l2-normalize x -> g_xn + g_A(fp16)
//   blocks [TOKENS/8, +CODES/8):     g_B = fp16(embed)
// 256 threads = 8 warps = 8 rows per block.
// ---------------------------------------------------------------------------
__global__ void __launch_bounds__(256)
k_prep(const float* __restrict__ x, const float* __restrict__ embed) {
    int warp = threadIdx.x >> 5;
    int lane = threadIdx.x & 31;
    int b = blockIdx.x;
    if (b >= TOKENS / 8) {
        int c = (b - TOKENS / 8) * 8 + warp;
        const float4* row = (const float4*)(embed + (size_t)c * DIM);
        __half* rB = g_B + (size_t)c * DIM;
        #pragma unroll
        for (int j = 0; j < 4; j++) {
            int idx = lane + j * 32;           // float4 index 0..127
            float4 a = row[idx];
            *(__half2*)(rB + idx * 4)     = __half2(__float2half_rn(a.x), __float2half_rn(a.y));
            *(__half2*)(rB + idx * 4 + 2) = __half2(__float2half_rn(a.z), __float2half_rn(a.w));
        }
        return;
    }
    int t = b * 8 + warp;
    const float4* row = (const float4*)(x + (size_t)t * DIM);
    float4 a[4];
    float ss = 0.0f;
    #pragma unroll
    for (int j = 0; j < 4; j++) {
        a[j] = row[lane + j * 32];
        ss += a[j].x * a[j].x + a[j].y * a[j].y + a[j].z * a[j].z + a[j].w * a[j].w;
    }
    #pragma unroll
    for (int o = 16; o > 0; o >>= 1) ss += __shfl_xor_sync(0xffffffffu, ss, o);
    float inv = 1.0f / fmaxf(sqrtf(ss), 1e-6f);
    float4* oxn = (float4*)(g_xn + (size_t)t * DIM);
    __half* rA = g_A + (size_t)t * DIM;
    #pragma unroll
    for (int j = 0; j < 4; j++) {
        int idx = lane + j * 32;
        float4 v = make_float4(a[j].x * inv, a[j].y * inv, a[j].z * inv, a[j].w * inv);
        oxn[idx] = v;
        *(__half2*)(rA + idx * 4)     = __half2(__float2half_rn(v.x), __float2half_rn(v.y));
        *(__half2*)(rA + idx * 4 + 2) = __half2(__float2half_rn(v.z), __float2half_rn(v.w));
    }
}

// ---------------------------------------------------------------------------
// K2: dist = g_A @ g_B^T via mma.sync fp16 (HMMA), K=512, plus per-tile row max.
// R9-validated config: 128x128 tile, BK=64, 3-stage cp.async ring,
// 8 warps (2M x 4N), warp 64x32, 2 CTAs/SM, plain stores.
// Extra CTA row (blockIdx.y == 64): EMA decay-init (overlapped with GEMM wave 1).
// ---------------------------------------------------------------------------
#define BK       64
#define NITERS   (DIM / BK)            // 8
#define NSTAGES  3
#define ASTRIDE  72                    // fp16 elems per smem row (64 + 8 pad)
#define ATILE_B  (128 * ASTRIDE * 2)   // 18432 bytes
#define STAGE_B  (2 * ATILE_B)         // 36864 bytes (A + B)
#define SMEM_TOT (NSTAGES * STAGE_B)   // 110592 bytes

extern __shared__ char dyn_smem[];

__device__ __forceinline__ void load_tile(uint32_t sbase, int stage, int iter,
                                          int tid, int rowBase, int colBase) {
    int k0 = iter * BK;
    uint32_t st = sbase + stage * STAGE_B;
    #pragma unroll
    for (int i = 0; i < 8; i++) {
        int q = i * 256 + tid;            // 0..2047
        int isA = q < 1024;
        int qq = isA ? q : q - 1024;
        int row = qq >> 3;
        int seg = qq & 7;                 // 8 fp16 (16B) per seg
        const __half* src =
            (isA ? g_A + (size_t)(rowBase + row) * DIM
                 : g_B + (size_t)(colBase + row) * DIM) + k0 + seg * 8;
        uint32_t dst = st + (isA ? 0 : ATILE_B) + (row * ASTRIDE + seg * 8) * 2;
        cp16(dst, src);
    }
}

__global__ void __launch_bounds__(256, 2)
k_gemm_mma(float* __restrict__ dist,
           const float* __restrict__ cs, const float* __restrict__ ea,
           float* __restrict__ out_cs, float* __restrict__ out_ea) {
    int tid  = threadIdx.x;

    // ---- EMA init CTAs (wave-1 overlap) ----
    if (blockIdx.y == 64) {
        int gid = blockIdx.x * 256 + tid;            // 0..16383
        const float4* ea4 = (const float4*)ea;
        float4* oea4 = (float4*)out_ea;
        for (int i = gid; i < CODES * DIM / 4; i += 64 * 256) {
            float4 v = ea4[i];
            oea4[i] = make_float4(DECAYF * v.x, DECAYF * v.y, DECAYF * v.z, DECAYF * v.w);
        }
        float local = 0.0f;
        if (gid < CODES / 4) {
            float4 v = ((const float4*)cs)[gid];
            float4 w = make_float4(DECAYF * v.x, DECAYF * v.y, DECAYF * v.z, DECAYF * v.w);
            ((float4*)out_cs)[gid] = w;
            local = w.x + w.y + w.z + w.w;
        }
        #pragma unroll
        for (int o = 16; o > 0; o >>= 1) local += __shfl_xor_sync(0xffffffffu, local, o);
        if ((tid & 31) == 0 && local != 0.0f) atomicAdd(&g_dsum, local);
        return;
    }

    __shared__ float s_rm[128][4];
    uint32_t sbase = smem_u32(dyn_smem);
    int wid  = tid >> 5;
    int lane = tid & 31;
    int warpM = wid >> 2;      // 0..1  (64 rows each)
    int warpN = wid & 3;       // 0..3  (32 cols each)
    int rowBase = blockIdx.y * 128;
    int colBase = blockIdx.x * 128;

    float acc[4][4][4];
    #pragma unroll
    for (int mi = 0; mi < 4; mi++)
        #pragma unroll
        for (int ni = 0; ni < 4; ni++)
            #pragma unroll
            for (int r = 0; r < 4; r++) acc[mi][ni][r] = 0.0f;

    int amat = lane >> 3, ar = lane & 7;
    int arow_in = (amat & 1) * 8 + ar;
    int ak_in   = (amat >> 1) * 8;
    int ml = lane & 15;
    int brow_in = ml & 7;
    int bk_in   = (ml >> 3) * 8;

    load_tile(sbase, 0, 0, tid, rowBase, colBase);
    cp_commit();
    load_tile(sbase, 1, 1, tid, rowBase, colBase);
    cp_commit();

    for (int it = 0; it < NITERS; it++) {
        int stage = it % NSTAGES;
        cp_wait1();
        __syncthreads();
        if (it + 2 < NITERS)
            load_tile(sbase, (it + 2) % NSTAGES, it + 2, tid, rowBase, colBase);
        cp_commit();

        uint32_t sA = sbase + stage * STAGE_B;
        uint32_t sB = sA + ATILE_B;
        #pragma unroll
        for (int ks = 0; ks < 4; ks++) {
            uint32_t a0[4], a1[4], a2[4], a3[4];
            #pragma unroll
            for (int mi = 0; mi < 4; mi++) {
                uint32_t addr = sA +
                    ((warpM * 64 + mi * 16 + arow_in) * ASTRIDE + ks * 16 + ak_in) * 2;
                ldsm_x4(a0[mi], a1[mi], a2[mi], a3[mi], addr);
            }
            uint32_t b0[4], b1[4];
            #pragma unroll
            for (int ni = 0; ni < 4; ni++) {
                uint32_t addr = sB +
                    ((warpN * 32 + ni * 8 + brow_in) * ASTRIDE + ks * 16 + bk_in) * 2;
                ldsm_x2(b0[ni], b1[ni], addr);
            }
            #pragma unroll
            for (int mi = 0; mi < 4; mi++)
                #pragma unroll
                for (int ni = 0; ni < 4; ni++)
                    mma_fp16(acc[mi][ni][0], acc[mi][ni][1], acc[mi][ni][2], acc[mi][ni][3],
                             a0[mi], a1[mi], a2[mi], a3[mi], b0[ni], b1[ni]);
        }
    }

    // Epilogue: write dist + per-warp row maxes
    int g = lane >> 2;
    int cq = (lane & 3) * 2;
    #pragma unroll
    for (int mi = 0; mi < 4; mi++) {
        int r0 = rowBase + warpM * 64 + mi * 16 + g;
        float mlo = -INFINITY, mhi = -INFINITY;
        #pragma unroll
        for (int ni = 0; ni < 4; ni++) {
            int cc = colBase + warpN * 32 + ni * 8 + cq;
            *(float2*)(dist + (size_t)r0 * CODES + cc) =
                make_float2(acc[mi][ni][0], acc[mi][ni][1]);
            *(float2*)(dist + (size_t)(r0 + 8) * CODES + cc) =
                make_float2(acc[mi][ni][2], acc[mi][ni][3]);
            mlo = fmaxf(mlo, fmaxf(acc[mi][ni][0], acc[mi][ni][1]));
            mhi = fmaxf(mhi, fmaxf(acc[mi][ni][2], acc[mi][ni][3]));
        }
        #pragma unroll
        for (int o = 1; o < 4; o <<= 1) {
            mlo = fmaxf(mlo, __shfl_xor_sync(0xffffffffu, mlo, o));
            mhi = fmaxf(mhi, __shfl_xor_sync(0xffffffffu, mhi, o));
        }
        if ((lane & 3) == 0) {
            s_rm[warpM * 64 + mi * 16 + g][warpN]     = mlo;
            s_rm[warpM * 64 + mi * 16 + g + 8][warpN] = mhi;
        }
    }
    __syncthreads();
    if (tid < 128) {
        float m = fmaxf(fmaxf(s_rm[tid][0], s_rm[tid][1]),
                        fmaxf(s_rm[tid][2], s_rm[tid][3]));
        g_tilemax[(size_t)(rowBase + tid) * 64 + blockIdx.x] = m;
    }
}

// ---------------------------------------------------------------------------
// K3: per-row candidate refinement + exact fp32 argmax + quantize gather
//     + fused EMA scatter. Block 0 also publishes denom and resets g_dsum.
// One block (128 threads) per token row. 64 tiles of 128 cols.
// ---------------------------------------------------------------------------
__global__ void __launch_bounds__(128)
k_select(const float* __restrict__ dist, const float* __restrict__ embed,
         float* __restrict__ out_ind, float* __restrict__ out_q,
         float* __restrict__ out_cs, float* __restrict__ out_ea) {
    int t = blockIdx.x;
    int tid = threadIdx.x;
    int wid = tid >> 5, lane = tid & 31;

    if (t == 0 && tid == 0) {
        // All k_gemm_mma (incl. EMA-init CTAs) atomics completed.
        g_denom = g_dsum + OMDF * (float)TOKENS;
        g_dsum = 0.0f;   // restore invariant for next launch/replay
    }

    __shared__ float s_tm[64];
    __shared__ float s_M;
    __shared__ int   s_cand[64];
    __shared__ int   s_ncand;
    __shared__ float s_red[4];
    __shared__ int   s_best;

    if (tid < 64) s_tm[tid] = g_tilemax[(size_t)t * 64 + tid];
    if (tid == 0) s_ncand = 0;
    __syncthreads();
    if (tid < 32) {
        float m = fmaxf(s_tm[tid], s_tm[tid + 32]);
        #pragma unroll
        for (int o = 16; o > 0; o >>= 1) m = fmaxf(m, __shfl_xor_sync(0xffffffffu, m, o));
        if (tid == 0) s_M = m;
    }
    __syncthreads();
    float thr = s_M - MARGIN;
    const float* drow = dist + (size_t)t * CODES;
    for (int tile = 0; tile < 64; tile++) {
        if (s_tm[tile] > thr) {
            float v = drow[tile * 128 + tid];
            if (v > thr) {
                int p = atomicAdd(&s_ncand, 1);
                if (p < 64) s_cand[p] = tile * 128 + tid;
            }
        }
    }
    __syncthreads();
    int nc = min(s_ncand, 64);

    float4 xv = ((const float4*)(g_xn + (size_t)t * DIM))[tid];
    float bestv = -INFINITY;
    int   besti = CODES;
    for (int ci = 0; ci < nc; ci++) {
        int c = s_cand[ci];
        float4 ev = ((const float4*)(embed + (size_t)c * DIM))[tid];
        float p = xv.x * ev.x + xv.y * ev.y + xv.z * ev.z + xv.w * ev.w;
        #pragma unroll
        for (int o = 16; o > 0; o >>= 1) p += __shfl_xor_sync(0xffffffffu, p, o);
        if (lane == 0) s_red[wid] = p;
        __syncthreads();
        if (tid == 0) {
            float d = (s_red[0] + s_red[1]) + (s_red[2] + s_red[3]);
            if (d > bestv || (d == bestv && c < besti)) { bestv = d; besti = c; }
        }
        __syncthreads();
    }
    if (tid == 0) {
        g_ind[t] = besti;
        out_ind[t] = (float)besti;
        s_best = besti;
        atomicAdd(out_cs + besti, OMDF);
    }
    __syncthreads();
    int best = s_best;
    // quantize gather
    float4 ev = ((const float4*)(embed + (size_t)best * DIM))[tid];
    ((float4*)(out_q + (size_t)t * DIM))[tid] = ev;
    // fused EMA scatter: out_ea[best] += (1-decay) * xn
    float* er = out_ea + (size_t)best * DIM + tid * 4;
    atomicAdd(er + 0, OMDF * xv.x);
    atomicAdd(er + 1, OMDF * xv.y);
    atomicAdd(er + 2, OMDF * xv.z);
    atomicAdd(er + 3, OMDF * xv.w);
}

// ---------------------------------------------------------------------------
// K7: new_embed = l2norm(new_embed_avg / smoothed), one WARP per row.
// 256 threads = 8 warps = 8 rows per block; no block barriers.
// ---------------------------------------------------------------------------
__global__ void __launch_bounds__(256)
k_newembed(const float* __restrict__ out_cs, const float* __restrict__ out_ea,
           float* __restrict__ out_e) {
    int warp = threadIdx.x >> 5;
    int lane = threadIdx.x & 31;
    int c = blockIdx.x * 8 + warp;
    float denom = g_denom;
    float smoothed = (out_cs[c] + EPSF) / (denom + (float)CODES * EPSF) * denom;
    float invs = 1.0f / smoothed;
    const float4* row = (const float4*)(out_ea + (size_t)c * DIM);
    float4 w[4];
    float ss = 0.0f;
    #pragma unroll
    for (int j = 0; j < 4; j++) {
        float4 v = row[lane + j * 32];
        w[j] = make_float4(v.x * invs, v.y * invs, v.z * invs, v.w * invs);
        ss += w[j].x * w[j].x + w[j].y * w[j].y + w[j].z * w[j].z + w[j].w * w[j].w;
    }
    #pragma unroll
    for (int o = 16; o > 0; o >>= 1) ss += __shfl_xor_sync(0xffffffffu, ss, o);
    float inv = 1.0f / fmaxf(sqrtf(ss), 1e-6f);
    float4* orow = (float4*)(out_e + (size_t)c * DIM);
    #pragma unroll
    for (int j = 0; j < 4; j++) {
        orow[lane + j * 32] =
            make_float4(w[j].x * inv, w[j].y * inv, w[j].z * inv, w[j].w * inv);
    }
}

// ---------------------------------------------------------------------------
extern "C" void kernel_launch(void* const* d_in, const int* in_sizes, int n_in,
                              void* d_out, int out_size) {
    const float* x     = (const float*)d_in[0];
    const float* embed = (const float*)d_in[1];
    const float* cs    = (const float*)d_in[2];
    const float* ea    = (const float*)d_in[3];
    float* out = (float*)d_out;

    cudaFuncSetAttribute(k_gemm_mma, cudaFuncAttributeMaxDynamicSharedMemorySize,
                         SMEM_TOT);

    k_prep<<<(TOKENS + CODES) / 8, 256>>>(x, embed);
    k_gemm_mma<<<dim3(CODES / 128, TOKENS / 128 + 1), 256, SMEM_TOT>>>(
        out + OFF_DIST, cs, ea, out + OFF_CS, out + OFF_EA);
    k_select<<<TOKENS, 128>>>(out + OFF_DIST, embed, out + OFF_IND, out + OFF_Q,
                              out + OFF_CS, out + OFF_EA);
    k_newembed<<<CODES / 8, 256>>>(out + OFF_CS, out + OFF_EA, out + OFF_E);
}